// round 10
// baseline (speedup 1.0000x reference)
#include <cuda_runtime.h>
#include <cuda_bf16.h>
#include <stdint.h>
#include <math.h>

// Problem constants
#define BATCH   2
#define SEQ     2048
#define DMODEL  2048
#define NHEADS  16
#define DHEAD   128
#define NTOK    (BATCH * SEQ)        // 4096 tokens

// ---------------------------------------------------------------------------
// Scratch buffers (static device globals; no runtime allocation allowed)
// ---------------------------------------------------------------------------
__device__ float g_Q[(size_t)NTOK * DMODEL];
__device__ float g_K[(size_t)NTOK * DMODEL];
__device__ float g_V[(size_t)NTOK * DMODEL];
__device__ float g_C[(size_t)NTOK * DMODEL];

// ===========================================================================
// Helpers
// ===========================================================================
__device__ __forceinline__ uint32_t smem_to_u32(const void* p) {
    uint32_t a;
    asm("{ .reg .u64 t; cvta.to.shared.u64 t, %1; cvt.u32.u64 %0, t; }"
        : "=r"(a) : "l"(p));
    return a;
}

#define LDSM_X4(r0, r1, r2, r3, addr) \
    asm volatile("ldmatrix.sync.aligned.m8n8.x4.shared.b16 {%0,%1,%2,%3}, [%4];" \
                 : "=r"(r0), "=r"(r1), "=r"(r2), "=r"(r3) : "r"(addr))

#define LDSM_X4_T(r0, r1, r2, r3, addr) \
    asm volatile("ldmatrix.sync.aligned.m8n8.x4.trans.shared.b16 {%0,%1,%2,%3}, [%4];" \
                 : "=r"(r0), "=r"(r1), "=r"(r2), "=r"(r3) : "r"(addr))

#define MMA_BF16(d, a, b0, b1) \
    asm volatile("mma.sync.aligned.m16n8k16.row.col.f32.bf16.bf16.f32 " \
                 "{%0,%1,%2,%3}, {%4,%5,%6,%7}, {%8,%9}, {%0,%1,%2,%3};" \
                 : "+f"((d)[0]), "+f"((d)[1]), "+f"((d)[2]), "+f"((d)[3]) \
                 : "r"((a)[0]), "r"((a)[1]), "r"((a)[2]), "r"((a)[3]), \
                   "r"(b0), "r"(b1))

// Split two floats into packed bf16 hi pair (returned, low half = first arg)
// and lo (residual) pair.
__device__ __forceinline__ uint32_t packsplit2(float a, float b, uint32_t& lo_out) {
    __nv_bfloat16 ha = __float2bfloat16_rn(a);
    __nv_bfloat16 hb = __float2bfloat16_rn(b);
    float la = a - __bfloat162float(ha);
    float lb = b - __bfloat162float(hb);
    __nv_bfloat16 hla = __float2bfloat16_rn(la);
    __nv_bfloat16 hlb = __float2bfloat16_rn(lb);
    lo_out = ((uint32_t)__bfloat16_as_ushort(hlb) << 16) |
             (uint32_t)__bfloat16_as_ushort(hla);
    return ((uint32_t)__bfloat16_as_ushort(hb) << 16) |
           (uint32_t)__bfloat16_as_ushort(ha);
}

// ===========================================================================
// Tensor-core GEMM via mma.sync (bf16 x2 split): Y[M,N] = X[M,K] @ W[N,K]^T
// (unchanged from R8 — proven: rel_err 2.2e-5)
// ===========================================================================
#define MM_BM 128
#define MM_BN 128
#define MM_BK 32
#define MM_AHI 0
#define MM_ALO 8192
#define MM_BHI 16384
#define MM_BLO 24576
#define MM_STAGE 32768
#define MM_SMEM (2 * MM_STAGE)     // 65536 bytes

__device__ __forceinline__ uint32_t sw_off(int row, int ch) {
    return (uint32_t)(row * 64 + ((ch ^ ((row >> 1) & 3)) << 4));
}

__global__ __launch_bounds__(256, 1)
void gemm_mma_kernel(const float* __restrict__ X,
                     const float* __restrict__ W,
                     float* __restrict__ Y,
                     int M, int N, int K)
{
    extern __shared__ char smem[];
    const uint32_t smem_u32 = smem_to_u32(smem);

    const int tid  = threadIdx.x;
    const int lane = tid & 31;
    const int warp = tid >> 5;
    const int wm   = warp & 3;
    const int wn   = warp >> 2;
    const int bm   = blockIdx.y * MM_BM;
    const int bn   = blockIdx.x * MM_BN;

    const int lrow  = tid >> 1;
    const int lhalf = tid & 1;

    const float* Arow = X + (size_t)(bm + lrow) * K + lhalf * 16;
    const float* Brow = W + (size_t)(bn + lrow) * K + lhalf * 16;

    float4 ra[4], rb[4];
    const int nchunk = K / MM_BK;

#pragma unroll
    for (int j = 0; j < 4; ++j) {
        ra[j] = *(const float4*)&Arow[j * 4];
        rb[j] = *(const float4*)&Brow[j * 4];
    }

    float acc[2][8][4];
#pragma unroll
    for (int mf = 0; mf < 2; ++mf)
#pragma unroll
        for (int nf = 0; nf < 8; ++nf)
#pragma unroll
            for (int q = 0; q < 4; ++q)
                acc[mf][nf][q] = 0.0f;

    for (int c = 0; c < nchunk; ++c) {
        const int s = c & 1;
        char* sbuf = smem + s * MM_STAGE;

#pragma unroll
        for (int j2 = 0; j2 < 2; ++j2) {
            const int ch = lhalf * 2 + j2;
            uint32_t aoff = sw_off(lrow, ch);
            uint4 hi, lo;
            hi.x = packsplit2(ra[2 * j2].x,     ra[2 * j2].y,     lo.x);
            hi.y = packsplit2(ra[2 * j2].z,     ra[2 * j2].w,     lo.y);
            hi.z = packsplit2(ra[2 * j2 + 1].x, ra[2 * j2 + 1].y, lo.z);
            hi.w = packsplit2(ra[2 * j2 + 1].z, ra[2 * j2 + 1].w, lo.w);
            *(uint4*)(sbuf + MM_AHI + aoff) = hi;
            *(uint4*)(sbuf + MM_ALO + aoff) = lo;
            hi.x = packsplit2(rb[2 * j2].x,     rb[2 * j2].y,     lo.x);
            hi.y = packsplit2(rb[2 * j2].z,     rb[2 * j2].w,     lo.y);
            hi.z = packsplit2(rb[2 * j2 + 1].x, rb[2 * j2 + 1].y, lo.z);
            hi.w = packsplit2(rb[2 * j2 + 1].z, rb[2 * j2 + 1].w, lo.w);
            *(uint4*)(sbuf + MM_BHI + aoff) = hi;
            *(uint4*)(sbuf + MM_BLO + aoff) = lo;
        }
        __syncthreads();

        if (c + 1 < nchunk) {
            const float* An = Arow + (size_t)(c + 1) * MM_BK;
            const float* Bn = Brow + (size_t)(c + 1) * MM_BK;
#pragma unroll
            for (int j = 0; j < 4; ++j) {
                ra[j] = *(const float4*)&An[j * 4];
                rb[j] = *(const float4*)&Bn[j * 4];
            }
        }

        const uint32_t sAhi = smem_u32 + s * MM_STAGE + MM_AHI;
        const uint32_t sAlo = smem_u32 + s * MM_STAGE + MM_ALO;
        const uint32_t sBhi = smem_u32 + s * MM_STAGE + MM_BHI;
        const uint32_t sBlo = smem_u32 + s * MM_STAGE + MM_BLO;

#pragma unroll
        for (int ks = 0; ks < 2; ++ks) {
            uint32_t ah[2][4], al[2][4];
#pragma unroll
            for (int mf = 0; mf < 2; ++mf) {
                int row = wm * 32 + mf * 16 + (lane & 15);
                int ch  = ks * 2 + (lane >> 4);
                uint32_t off = sw_off(row, ch);
                LDSM_X4(ah[mf][0], ah[mf][1], ah[mf][2], ah[mf][3], sAhi + off);
                LDSM_X4(al[mf][0], al[mf][1], al[mf][2], al[mf][3], sAlo + off);
            }
            uint32_t bh[4][4], bl[4][4];
#pragma unroll
            for (int nf2 = 0; nf2 < 4; ++nf2) {
                int row = wn * 64 + nf2 * 16 + (lane & 15);
                int ch  = ks * 2 + (lane >> 4);
                uint32_t off = sw_off(row, ch);
                LDSM_X4(bh[nf2][0], bh[nf2][1], bh[nf2][2], bh[nf2][3], sBhi + off);
                LDSM_X4(bl[nf2][0], bl[nf2][1], bl[nf2][2], bl[nf2][3], sBlo + off);
            }
#pragma unroll
            for (int mf = 0; mf < 2; ++mf)
#pragma unroll
                for (int nf2 = 0; nf2 < 4; ++nf2)
#pragma unroll
                    for (int sub = 0; sub < 2; ++sub) {
                        float* d = acc[mf][nf2 * 2 + sub];
                        MMA_BF16(d, ah[mf], bh[nf2][sub], bh[nf2][sub + 2]);
                        MMA_BF16(d, ah[mf], bl[nf2][sub], bl[nf2][sub + 2]);
                        MMA_BF16(d, al[mf], bh[nf2][sub], bh[nf2][sub + 2]);
                    }
        }
        __syncthreads();
    }

#pragma unroll
    for (int mf = 0; mf < 2; ++mf) {
        int r0 = bm + wm * 32 + mf * 16 + (lane >> 2);
#pragma unroll
        for (int nf = 0; nf < 8; ++nf) {
            int col = bn + wn * 64 + nf * 8 + (lane & 3) * 2;
            float2 v0 = make_float2(acc[mf][nf][0], acc[mf][nf][1]);
            float2 v1 = make_float2(acc[mf][nf][2], acc[mf][nf][3]);
            *(float2*)&Y[(size_t)r0 * N + col]       = v0;
            *(float2*)&Y[(size_t)(r0 + 8) * N + col] = v1;
        }
    }
}

// ---------------------------------------------------------------------------
// RoPE: in-place on Q and K, layout (token, h*128 + d). (unchanged)
// ---------------------------------------------------------------------------
__global__ void rope_kernel(float* __restrict__ Q, float* __restrict__ K,
                            const float* __restrict__ cosT,
                            const float* __restrict__ sinT)
{
    int i = blockIdx.x * blockDim.x + threadIdx.x;
    if (i >= NTOK * NHEADS * 64) return;
    int d     = i & 63;
    int h     = (i >> 6) & (NHEADS - 1);
    int token = i >> 10;
    int s     = token & (SEQ - 1);

    int base = token * DMODEL + h * DHEAD;
    float c1 = cosT[s * DHEAD + d];
    float s1 = sinT[s * DHEAD + d];
    float c2 = cosT[s * DHEAD + d + 64];
    float s2 = sinT[s * DHEAD + d + 64];

    float q1 = Q[base + d], q2 = Q[base + d + 64];
    Q[base + d]      = q1 * c1 - q2 * s1;
    Q[base + d + 64] = q2 * c2 + q1 * s2;

    float k1 = K[base + d], k2 = K[base + d + 64];
    K[base + d]      = k1 * c1 - k2 * s1;
    K[base + d + 64] = k2 * c2 + k1 * s2;
}

// ===========================================================================
// Causal flash attention via mma.sync bf16 (hi/lo split).
// Block = (qtile, head, batch): 64 q rows x 64 kv cols per iteration.
// 8 warps: wm = warp&3 (16 q-rows), wn = warp>>2.
//   QK^T: warp computes S[16 x 32] (wn = 32-col slice)
//   PV:   warp computes O[16 x 64] (wn = 64-dim slice), P staged via smem.
// Softmax row stats are reduced ACROSS the wn=0/wn=1 warp pair through smem
// (each warp only owns half of each score row).
// K and V share one smem buffer (load K -> QK -> softmax+V load -> PV).
// All tiles swizzled: chunk' = ch ^ (row & 7)  (16B chunks).
// ===========================================================================
#define FB_QH  0
#define FB_QL  16384
#define FB_KVH 32768
#define FB_KVL 49152
#define FB_PH  65536
#define FB_PL  73728
#define FB_MX  81920
#define FB_RS  82432
#define FB_SMEM 82944

// A-fragment x4 address: matrix m: rows base+(m&1)*8, chunk base+(m>>1)
__device__ __forceinline__ uint32_t a_addr(uint32_t plane, int rowbase,
                                           int chbase, int lane, int rowbytes) {
    int m  = lane >> 3;
    int r  = rowbase + ((m & 1) << 3) + (lane & 7);
    int ch = chbase + (m >> 1);
    return plane + (uint32_t)(r * rowbytes + ((ch ^ (r & 7)) << 4));
}
// B-fragment x4 address: matrix m: rows(n) base+(m>>1)*8, chunk(k) base+(m&1)
__device__ __forceinline__ uint32_t b_addr(uint32_t plane, int rowbase,
                                           int chbase, int lane, int rowbytes) {
    int m  = lane >> 3;
    int r  = rowbase + ((m >> 1) << 3) + (lane & 7);
    int ch = chbase + (m & 1);
    return plane + (uint32_t)(r * rowbytes + ((ch ^ (r & 7)) << 4));
}

// Load 64 x 128 fp32 tile (leading dim DMODEL) -> two swizzled bf16 planes.
__device__ __forceinline__ void load_tile64_split(
    const float* __restrict__ src, char* smem,
    uint32_t dstH, uint32_t dstL, int tid, float scale)
{
    int r    = tid >> 2;        // 0..63
    int part = tid & 3;         // floats part*32 .. +31
    const float* row = src + (size_t)r * DMODEL + part * 32;
#pragma unroll
    for (int c = 0; c < 4; ++c) {
        float4 v0 = *(const float4*)&row[c * 8];
        float4 v1 = *(const float4*)&row[c * 8 + 4];
        v0.x *= scale; v0.y *= scale; v0.z *= scale; v0.w *= scale;
        v1.x *= scale; v1.y *= scale; v1.z *= scale; v1.w *= scale;
        uint4 hi, lo;
        hi.x = packsplit2(v0.x, v0.y, lo.x);
        hi.y = packsplit2(v0.z, v0.w, lo.y);
        hi.z = packsplit2(v1.x, v1.y, lo.z);
        hi.w = packsplit2(v1.z, v1.w, lo.w);
        int ch = part * 4 + c;
        uint32_t off = (uint32_t)(r * 256 + ((ch ^ (r & 7)) << 4));
        *(uint4*)(smem + dstH + off) = hi;
        *(uint4*)(smem + dstL + off) = lo;
    }
}

__global__ __launch_bounds__(256, 2)
void flash_attn_mma_kernel(const float* __restrict__ Q,
                           const float* __restrict__ K,
                           const float* __restrict__ V,
                           float* __restrict__ O)
{
    extern __shared__ char smem[];
    const uint32_t su = smem_to_u32(smem);
    float* smx = (float*)(smem + FB_MX);   // [2][64] row maxima (wn halves)
    float* srs = (float*)(smem + FB_RS);   // [2][64] row partial sums

    const int tid  = threadIdx.x;
    const int lane = tid & 31;
    const int warp = tid >> 5;
    const int wm   = warp & 3;
    const int wn   = warp >> 2;
    // longest q-tiles first to shrink the wave tail
    const int qt   = (int)gridDim.x - 1 - (int)blockIdx.x;
    const int h    = blockIdx.y;
    const int b    = blockIdx.z;
    const int q0   = qt * 64;
    const float scale = 0.08838834764831845f;   // 1/sqrt(128)

    const float* Qb = Q + (size_t)(b * SEQ) * DMODEL + h * DHEAD;
    const float* Kb = K + (size_t)(b * SEQ) * DMODEL + h * DHEAD;
    const float* Vb = V + (size_t)(b * SEQ) * DMODEL + h * DHEAD;
    float*       Ob = O + (size_t)(b * SEQ) * DMODEL + h * DHEAD;

    // Q tile (pre-scaled) -> smem once
    load_tile64_split(Qb + (size_t)q0 * DMODEL, smem, FB_QH, FB_QL, tid, scale);

    const int r_lo = lane >> 2;        // 0..7
    const int pr0  = wm * 16 + r_lo;   // local q-row (first half)
    const int pr1  = pr0 + 8;
    float m0 = -1e30f, m1 = -1e30f, l0 = 0.0f, l1 = 0.0f;
    float acc[8][4];
#pragma unroll
    for (int ng = 0; ng < 8; ++ng)
#pragma unroll
        for (int q = 0; q < 4; ++q)
            acc[ng][q] = 0.0f;

    for (int kt = 0; kt <= qt; ++kt) {
        const int k0 = kt * 64;

        __syncthreads();   // A: prev-iter V/P reads done (first iter: Q ordered)
        load_tile64_split(Kb + (size_t)k0 * DMODEL, smem, FB_KVH, FB_KVL, tid, 1.0f);
        __syncthreads();   // B: K visible

        // ---- S = Q . K^T  (3-plane bf16 split) ----
        float sacc[4][4];
#pragma unroll
        for (int nf = 0; nf < 4; ++nf)
#pragma unroll
            for (int q = 0; q < 4; ++q)
                sacc[nf][q] = 0.0f;

#pragma unroll
        for (int ks = 0; ks < 8; ++ks) {
            uint32_t qh[4], ql[4];
            uint32_t qa = a_addr(su + FB_QH, wm * 16, ks * 2, lane, 256);
            LDSM_X4(qh[0], qh[1], qh[2], qh[3], qa);
            LDSM_X4(ql[0], ql[1], ql[2], ql[3], qa + (FB_QL - FB_QH));
#pragma unroll
            for (int g = 0; g < 2; ++g) {
                uint32_t kh[4], kl[4];
                uint32_t ka = b_addr(su + FB_KVH, wn * 32 + g * 16, ks * 2, lane, 256);
                LDSM_X4(kh[0], kh[1], kh[2], kh[3], ka);
                LDSM_X4(kl[0], kl[1], kl[2], kl[3], ka + (FB_KVL - FB_KVH));
#pragma unroll
                for (int sub = 0; sub < 2; ++sub) {
                    float* d = sacc[g * 2 + sub];
                    MMA_BF16(d, qh, kh[2 * sub], kh[2 * sub + 1]);
                    MMA_BF16(d, qh, kl[2 * sub], kl[2 * sub + 1]);
                    MMA_BF16(d, ql, kh[2 * sub], kh[2 * sub + 1]);
                }
            }
        }

        // ---- causal mask (diagonal tile) ----
        if (kt == qt) {
#pragma unroll
            for (int nf = 0; nf < 4; ++nf)
#pragma unroll
                for (int j = 0; j < 4; ++j) {
                    int rw = q0 + wm * 16 + r_lo + ((j >> 1) << 3);
                    int cl = k0 + wn * 32 + nf * 8 + 2 * (lane & 3) + (j & 1);
                    if (cl > rw) sacc[nf][j] = -1e30f;
                }
        }

        // ---- local (half-row) max, quad-reduced ----
        float mx0 = -1e30f, mx1 = -1e30f;
#pragma unroll
        for (int nf = 0; nf < 4; ++nf) {
            mx0 = fmaxf(mx0, fmaxf(sacc[nf][0], sacc[nf][1]));
            mx1 = fmaxf(mx1, fmaxf(sacc[nf][2], sacc[nf][3]));
        }
        mx0 = fmaxf(mx0, __shfl_xor_sync(0xFFFFFFFFu, mx0, 1));
        mx0 = fmaxf(mx0, __shfl_xor_sync(0xFFFFFFFFu, mx0, 2));
        mx1 = fmaxf(mx1, __shfl_xor_sync(0xFFFFFFFFu, mx1, 1));
        mx1 = fmaxf(mx1, __shfl_xor_sync(0xFFFFFFFFu, mx1, 2));
        if ((lane & 3) == 0) {
            smx[wn * 64 + pr0] = mx0;
            smx[wn * 64 + pr1] = mx1;
        }
        __syncthreads();   // C: maxima visible; K reads done (V may overwrite)

        // ---- combine halves -> full-row max; rescale factors ----
        float mn0 = fmaxf(m0, fmaxf(smx[pr0], smx[64 + pr0]));
        float mn1 = fmaxf(m1, fmaxf(smx[pr1], smx[64 + pr1]));
        float al0 = __expf(m0 - mn0), al1 = __expf(m1 - mn1);
        m0 = mn0; m1 = mn1;

        // cooperative V load (overwrites K buffer; reads finished at C)
        load_tile64_split(Vb + (size_t)k0 * DMODEL, smem, FB_KVH, FB_KVL, tid, 1.0f);

        // ---- p = exp(s - m), store P planes, local row sums ----
        float rs0 = 0.0f, rs1 = 0.0f;
#pragma unroll
        for (int nf = 0; nf < 4; ++nf) {
            float p00 = __expf(sacc[nf][0] - mn0);
            float p01 = __expf(sacc[nf][1] - mn0);
            float p10 = __expf(sacc[nf][2] - mn1);
            float p11 = __expf(sacc[nf][3] - mn1);
            rs0 += p00 + p01;
            rs1 += p10 + p11;
            int pch = wn * 4 + nf;
            uint32_t lo, hi;
            hi = packsplit2(p00, p01, lo);
            uint32_t off0 = (uint32_t)(pr0 * 128 + ((pch ^ (pr0 & 7)) << 4) + 4 * (lane & 3));
            *(uint32_t*)(smem + FB_PH + off0) = hi;
            *(uint32_t*)(smem + FB_PL + off0) = lo;
            hi = packsplit2(p10, p11, lo);
            uint32_t off1 = (uint32_t)(pr1 * 128 + ((pch ^ (pr1 & 7)) << 4) + 4 * (lane & 3));
            *(uint32_t*)(smem + FB_PH + off1) = hi;
            *(uint32_t*)(smem + FB_PL + off1) = lo;
        }
        rs0 += __shfl_xor_sync(0xFFFFFFFFu, rs0, 1);
        rs0 += __shfl_xor_sync(0xFFFFFFFFu, rs0, 2);
        rs1 += __shfl_xor_sync(0xFFFFFFFFu, rs1, 1);
        rs1 += __shfl_xor_sync(0xFFFFFFFFu, rs1, 2);
        if ((lane & 3) == 0) {
            srs[wn * 64 + pr0] = rs0;
            srs[wn * 64 + pr1] = rs1;
        }

        // rescale accumulators while stores land
#pragma unroll
        for (int ng = 0; ng < 8; ++ng) {
            acc[ng][0] *= al0; acc[ng][1] *= al0;
            acc[ng][2] *= al1; acc[ng][3] *= al1;
        }

        __syncthreads();   // D: P, V, rs visible

        // ---- full-row sum update ----
        l0 = l0 * al0 + srs[pr0] + srs[64 + pr0];
        l1 = l1 * al1 + srs[pr1] + srs[64 + pr1];

        // ---- O += P . V  (3-plane bf16 split; V via ldmatrix.trans) ----
#pragma unroll
        for (int t = 0; t < 4; ++t) {
            uint32_t ph[4], pl[4];
            uint32_t pa = a_addr(su + FB_PH, wm * 16, t * 2, lane, 128);
            LDSM_X4(ph[0], ph[1], ph[2], ph[3], pa);
            LDSM_X4(pl[0], pl[1], pl[2], pl[3], pa + (FB_PL - FB_PH));
#pragma unroll
            for (int ng = 0; ng < 8; ng += 2) {
                uint32_t vh[4], vl[4];
                uint32_t va = a_addr(su + FB_KVH, t * 16, wn * 8 + ng, lane, 256);
                LDSM_X4_T(vh[0], vh[1], vh[2], vh[3], va);
                LDSM_X4_T(vl[0], vl[1], vl[2], vl[3], va + (FB_KVL - FB_KVH));
                MMA_BF16(acc[ng],     ph, vh[0], vh[1]);
                MMA_BF16(acc[ng],     ph, vl[0], vl[1]);
                MMA_BF16(acc[ng],     pl, vh[0], vh[1]);
                MMA_BF16(acc[ng + 1], ph, vh[2], vh[3]);
                MMA_BF16(acc[ng + 1], ph, vl[2], vl[3]);
                MMA_BF16(acc[ng + 1], pl, vh[2], vh[3]);
            }
        }
    }

    // ---- finalize ----
    float inv0 = 1.0f / l0, inv1 = 1.0f / l1;
    int row0 = q0 + wm * 16 + r_lo;
#pragma unroll
    for (int ng = 0; ng < 8; ++ng) {
        int col = wn * 64 + ng * 8 + 2 * (lane & 3);
        *(float2*)&Ob[(size_t)row0 * DMODEL + col] =
            make_float2(acc[ng][0] * inv0, acc[ng][1] * inv0);
        *(float2*)&Ob[(size_t)(row0 + 8) * DMODEL + col] =
            make_float2(acc[ng][2] * inv1, acc[ng][3] * inv1);
    }
}

// ---------------------------------------------------------------------------
// kernel_launch
// Inputs (metadata order): x, cos, sin, Wq, Wk, Wv, Wo  (all fp32)
// Output: (B, S, D_MODEL) fp32
// ---------------------------------------------------------------------------
extern "C" void kernel_launch(void* const* d_in, const int* in_sizes, int n_in,
                              void* d_out, int out_size)
{
    const float* x    = (const float*)d_in[0];
    const float* cosT = (const float*)d_in[1];
    const float* sinT = (const float*)d_in[2];
    const float* Wq   = (const float*)d_in[3];
    const float* Wk   = (const float*)d_in[4];
    const float* Wv   = (const float*)d_in[5];
    const float* Wo   = (const float*)d_in[6];
    float* out = (float*)d_out;

    float *qp, *kp, *vp, *cp;
    cudaGetSymbolAddress((void**)&qp, g_Q);
    cudaGetSymbolAddress((void**)&kp, g_K);
    cudaGetSymbolAddress((void**)&vp, g_V);
    cudaGetSymbolAddress((void**)&cp, g_C);

    cudaFuncSetAttribute(gemm_mma_kernel,
                         cudaFuncAttributeMaxDynamicSharedMemorySize, MM_SMEM);
    cudaFuncSetAttribute(flash_attn_mma_kernel,
                         cudaFuncAttributeMaxDynamicSharedMemorySize, FB_SMEM);

    dim3 ggrid(DMODEL / MM_BN, NTOK / MM_BM);   // (16, 32)

    // QKV projections (mma.sync bf16 x2-split)
    gemm_mma_kernel<<<ggrid, 256, MM_SMEM>>>(x, Wq, qp, NTOK, DMODEL, DMODEL);
    gemm_mma_kernel<<<ggrid, 256, MM_SMEM>>>(x, Wk, kp, NTOK, DMODEL, DMODEL);
    gemm_mma_kernel<<<ggrid, 256, MM_SMEM>>>(x, Wv, vp, NTOK, DMODEL, DMODEL);

    // RoPE on Q and K
    int rope_threads = NTOK * NHEADS * 64;
    rope_kernel<<<(rope_threads + 255) / 256, 256>>>(qp, kp, cosT, sinT);

    // Causal flash attention (tensor cores)
    dim3 fgrid(SEQ / 64, NHEADS, BATCH);   // (32, 16, 2)
    flash_attn_mma_kernel<<<fgrid, 256, FB_SMEM>>>(qp, kp, vp, cp);

    // Output projection -> d_out
    gemm_mma_kernel<<<ggrid, 256, MM_SMEM>>>(cp, Wo, out, NTOK, DMODEL, DMODEL);
}

// round 13
// speedup vs baseline: 1.7340x; 1.7340x over previous
#include <cuda_runtime.h>
#include <cuda_bf16.h>
#include <stdint.h>
#include <math.h>

// Problem constants
#define BATCH   2
#define SEQ     2048
#define DMODEL  2048
#define NHEADS  16
#define DHEAD   128
#define NTOK    (BATCH * SEQ)        // 4096 tokens
#define QSCALE  0.08838834764831845f // 1/sqrt(128)

// ---------------------------------------------------------------------------
// Scratch buffers (static device globals; no runtime allocation allowed)
// ---------------------------------------------------------------------------
__device__ float g_Q[(size_t)NTOK * DMODEL];
__device__ float g_K[(size_t)NTOK * DMODEL];
__device__ float g_V[(size_t)NTOK * DMODEL];
__device__ float g_C[(size_t)NTOK * DMODEL];
// bf16 hi/lo planes, pre-swizzled FA tile layout:
// [(b*16+h)*32 + tile][row 0..63][256B swizzled row]
#define PLANE_BYTES ((size_t)NTOK * DMODEL * 2)
__device__ uint8_t g_Qh[PLANE_BYTES], g_Ql[PLANE_BYTES];
__device__ uint8_t g_Kh[PLANE_BYTES], g_Kl[PLANE_BYTES];
__device__ uint8_t g_Vh[PLANE_BYTES], g_Vl[PLANE_BYTES];

// ===========================================================================
// Helpers
// ===========================================================================
__device__ __forceinline__ uint32_t smem_to_u32(const void* p) {
    uint32_t a;
    asm("{ .reg .u64 t; cvta.to.shared.u64 t, %1; cvt.u32.u64 %0, t; }"
        : "=r"(a) : "l"(p));
    return a;
}

#define LDSM_X4(r0, r1, r2, r3, addr) \
    asm volatile("ldmatrix.sync.aligned.m8n8.x4.shared.b16 {%0,%1,%2,%3}, [%4];" \
                 : "=r"(r0), "=r"(r1), "=r"(r2), "=r"(r3) : "r"(addr))

#define LDSM_X4_T(r0, r1, r2, r3, addr) \
    asm volatile("ldmatrix.sync.aligned.m8n8.x4.trans.shared.b16 {%0,%1,%2,%3}, [%4];" \
                 : "=r"(r0), "=r"(r1), "=r"(r2), "=r"(r3) : "r"(addr))

#define MMA_BF16(d, a, b0, b1) \
    asm volatile("mma.sync.aligned.m16n8k16.row.col.f32.bf16.bf16.f32 " \
                 "{%0,%1,%2,%3}, {%4,%5,%6,%7}, {%8,%9}, {%0,%1,%2,%3};" \
                 : "+f"((d)[0]), "+f"((d)[1]), "+f"((d)[2]), "+f"((d)[3]) \
                 : "r"((a)[0]), "r"((a)[1]), "r"((a)[2]), "r"((a)[3]), \
                   "r"(b0), "r"(b1))

__device__ __forceinline__ void cp16(uint32_t dst, const void* src) {
    asm volatile("cp.async.cg.shared.global [%0], [%1], 16;"
                 :: "r"(dst), "l"(src));
}
#define CP_COMMIT() asm volatile("cp.async.commit_group;" ::: "memory")
#define CP_WAIT0()  asm volatile("cp.async.wait_group 0;" ::: "memory")

// Split two floats into packed bf16 hi pair (low half = first arg) + lo pair.
__device__ __forceinline__ uint32_t packsplit2(float a, float b, uint32_t& lo_out) {
    __nv_bfloat16 ha = __float2bfloat16_rn(a);
    __nv_bfloat16 hb = __float2bfloat16_rn(b);
    float la = a - __bfloat162float(ha);
    float lb = b - __bfloat162float(hb);
    __nv_bfloat16 hla = __float2bfloat16_rn(la);
    __nv_bfloat16 hlb = __float2bfloat16_rn(lb);
    lo_out = ((uint32_t)__bfloat16_as_ushort(hlb) << 16) |
             (uint32_t)__bfloat16_as_ushort(hla);
    return ((uint32_t)__bfloat16_as_ushort(hb) << 16) |
           (uint32_t)__bfloat16_as_ushort(ha);
}

// ===========================================================================
// Tensor-core GEMM via mma.sync (bf16 x2 split): Y[M,N] = X[M,K] @ W[N,K]^T
// (unchanged — proven in R8: rel_err 2.2e-5)
// ===========================================================================
#define MM_BM 128
#define MM_BN 128
#define MM_BK 32
#define MM_AHI 0
#define MM_ALO 8192
#define MM_BHI 16384
#define MM_BLO 24576
#define MM_STAGE 32768
#define MM_SMEM (2 * MM_STAGE)     // 65536 bytes

__device__ __forceinline__ uint32_t sw_off(int row, int ch) {
    return (uint32_t)(row * 64 + ((ch ^ ((row >> 1) & 3)) << 4));
}

__global__ __launch_bounds__(256, 1)
void gemm_mma_kernel(const float* __restrict__ X,
                     const float* __restrict__ W,
                     float* __restrict__ Y,
                     int M, int N, int K)
{
    extern __shared__ char smem[];
    const uint32_t smem_u32 = smem_to_u32(smem);

    const int tid  = threadIdx.x;
    const int lane = tid & 31;
    const int warp = tid >> 5;
    const int wm   = warp & 3;
    const int wn   = warp >> 2;
    const int bm   = blockIdx.y * MM_BM;
    const int bn   = blockIdx.x * MM_BN;

    const int lrow  = tid >> 1;
    const int lhalf = tid & 1;

    const float* Arow = X + (size_t)(bm + lrow) * K + lhalf * 16;
    const float* Brow = W + (size_t)(bn + lrow) * K + lhalf * 16;

    float4 ra[4], rb[4];
    const int nchunk = K / MM_BK;

#pragma unroll
    for (int j = 0; j < 4; ++j) {
        ra[j] = *(const float4*)&Arow[j * 4];
        rb[j] = *(const float4*)&Brow[j * 4];
    }

    float acc[2][8][4];
#pragma unroll
    for (int mf = 0; mf < 2; ++mf)
#pragma unroll
        for (int nf = 0; nf < 8; ++nf)
#pragma unroll
            for (int q = 0; q < 4; ++q)
                acc[mf][nf][q] = 0.0f;

    for (int c = 0; c < nchunk; ++c) {
        const int s = c & 1;
        char* sbuf = smem + s * MM_STAGE;

#pragma unroll
        for (int j2 = 0; j2 < 2; ++j2) {
            const int ch = lhalf * 2 + j2;
            uint32_t aoff = sw_off(lrow, ch);
            uint4 hi, lo;
            hi.x = packsplit2(ra[2 * j2].x,     ra[2 * j2].y,     lo.x);
            hi.y = packsplit2(ra[2 * j2].z,     ra[2 * j2].w,     lo.y);
            hi.z = packsplit2(ra[2 * j2 + 1].x, ra[2 * j2 + 1].y, lo.z);
            hi.w = packsplit2(ra[2 * j2 + 1].z, ra[2 * j2 + 1].w, lo.w);
            *(uint4*)(sbuf + MM_AHI + aoff) = hi;
            *(uint4*)(sbuf + MM_ALO + aoff) = lo;
            hi.x = packsplit2(rb[2 * j2].x,     rb[2 * j2].y,     lo.x);
            hi.y = packsplit2(rb[2 * j2].z,     rb[2 * j2].w,     lo.y);
            hi.z = packsplit2(rb[2 * j2 + 1].x, rb[2 * j2 + 1].y, lo.z);
            hi.w = packsplit2(rb[2 * j2 + 1].z, rb[2 * j2 + 1].w, lo.w);
            *(uint4*)(sbuf + MM_BHI + aoff) = hi;
            *(uint4*)(sbuf + MM_BLO + aoff) = lo;
        }
        __syncthreads();

        if (c + 1 < nchunk) {
            const float* An = Arow + (size_t)(c + 1) * MM_BK;
            const float* Bn = Brow + (size_t)(c + 1) * MM_BK;
#pragma unroll
            for (int j = 0; j < 4; ++j) {
                ra[j] = *(const float4*)&An[j * 4];
                rb[j] = *(const float4*)&Bn[j * 4];
            }
        }

        const uint32_t sAhi = smem_u32 + s * MM_STAGE + MM_AHI;
        const uint32_t sAlo = smem_u32 + s * MM_STAGE + MM_ALO;
        const uint32_t sBhi = smem_u32 + s * MM_STAGE + MM_BHI;
        const uint32_t sBlo = smem_u32 + s * MM_STAGE + MM_BLO;

#pragma unroll
        for (int ks = 0; ks < 2; ++ks) {
            uint32_t ah[2][4], al[2][4];
#pragma unroll
            for (int mf = 0; mf < 2; ++mf) {
                int row = wm * 32 + mf * 16 + (lane & 15);
                int ch  = ks * 2 + (lane >> 4);
                uint32_t off = sw_off(row, ch);
                LDSM_X4(ah[mf][0], ah[mf][1], ah[mf][2], ah[mf][3], sAhi + off);
                LDSM_X4(al[mf][0], al[mf][1], al[mf][2], al[mf][3], sAlo + off);
            }
            uint32_t bh[4][4], bl[4][4];
#pragma unroll
            for (int nf2 = 0; nf2 < 4; ++nf2) {
                int row = wn * 64 + nf2 * 16 + (lane & 15);
                int ch  = ks * 2 + (lane >> 4);
                uint32_t off = sw_off(row, ch);
                LDSM_X4(bh[nf2][0], bh[nf2][1], bh[nf2][2], bh[nf2][3], sBhi + off);
                LDSM_X4(bl[nf2][0], bl[nf2][1], bl[nf2][2], bl[nf2][3], sBlo + off);
            }
#pragma unroll
            for (int mf = 0; mf < 2; ++mf)
#pragma unroll
                for (int nf2 = 0; nf2 < 4; ++nf2)
#pragma unroll
                    for (int sub = 0; sub < 2; ++sub) {
                        float* d = acc[mf][nf2 * 2 + sub];
                        MMA_BF16(d, ah[mf], bh[nf2][sub], bh[nf2][sub + 2]);
                        MMA_BF16(d, ah[mf], bl[nf2][sub], bl[nf2][sub + 2]);
                        MMA_BF16(d, al[mf], bh[nf2][sub], bh[nf2][sub + 2]);
                    }
        }
        __syncthreads();
    }

#pragma unroll
    for (int mf = 0; mf < 2; ++mf) {
        int r0 = bm + wm * 32 + mf * 16 + (lane >> 2);
#pragma unroll
        for (int nf = 0; nf < 8; ++nf) {
            int col = bn + wn * 64 + nf * 8 + (lane & 3) * 2;
            float2 v0 = make_float2(acc[mf][nf][0], acc[mf][nf][1]);
            float2 v1 = make_float2(acc[mf][nf][2], acc[mf][nf][3]);
            *(float2*)&Y[(size_t)r0 * N + col]       = v0;
            *(float2*)&Y[(size_t)(r0 + 8) * N + col] = v1;
        }
    }
}

// ===========================================================================
// RoPE + bf16 hi/lo plane conversion (Q scaled by 1/sqrt(128)), plus V planes.
// One thread per (token, head, 8-dim chunk): 4096*16*16 = 1,048,576 threads.
// Plane layout: [(b*16+h)*32 + tile][r=token&63][256B row, chunk ^ (r&7)].
// ===========================================================================
__global__ void rope_convert_kernel(const float* __restrict__ Q,
                                    const float* __restrict__ K,
                                    const float* __restrict__ V,
                                    const float* __restrict__ cosT,
                                    const float* __restrict__ sinT,
                                    uint8_t* __restrict__ Qh, uint8_t* __restrict__ Ql,
                                    uint8_t* __restrict__ Kh, uint8_t* __restrict__ Kl,
                                    uint8_t* __restrict__ Vh, uint8_t* __restrict__ Vl)
{
    int i = blockIdx.x * blockDim.x + threadIdx.x;
    if (i >= NTOK * NHEADS * 16) return;
    int ch    = i & 15;
    int h     = (i >> 4) & (NHEADS - 1);
    int token = i >> 8;                 // b*SEQ + s
    int s     = token & (SEQ - 1);
    int b     = token >> 11;
    int d0    = ch * 8;
    int r     = s & 63;
    int tile  = s >> 6;

    size_t pbase = ((((size_t)(b * NHEADS + h)) * 32 + tile) * 64 + r) * 256
                 + (uint32_t)((ch ^ (r & 7)) << 4);

    const float* xq = Q + (size_t)token * DMODEL + h * DHEAD;
    const float* xk = K + (size_t)token * DMODEL + h * DHEAD;
    const float* xv = V + (size_t)token * DMODEL + h * DHEAD;

    float q8[8], k8[8], v8[8];
#pragma unroll
    for (int j = 0; j < 8; ++j) {
        int d = d0 + j;
        float c  = cosT[s * DHEAD + d];
        float sn = sinT[s * DHEAD + d];
        int   p  = (d < 64) ? d + 64 : d - 64;
        float sg = (d < 64) ? -1.0f : 1.0f;
        q8[j] = (xq[d] * c + sg * xq[p] * sn) * QSCALE;
        k8[j] =  xk[d] * c + sg * xk[p] * sn;
        v8[j] =  xv[d];
    }

    uint4 hi, lo;
    hi.x = packsplit2(q8[0], q8[1], lo.x);
    hi.y = packsplit2(q8[2], q8[3], lo.y);
    hi.z = packsplit2(q8[4], q8[5], lo.z);
    hi.w = packsplit2(q8[6], q8[7], lo.w);
    *(uint4*)(Qh + pbase) = hi; *(uint4*)(Ql + pbase) = lo;

    hi.x = packsplit2(k8[0], k8[1], lo.x);
    hi.y = packsplit2(k8[2], k8[3], lo.y);
    hi.z = packsplit2(k8[4], k8[5], lo.z);
    hi.w = packsplit2(k8[6], k8[7], lo.w);
    *(uint4*)(Kh + pbase) = hi; *(uint4*)(Kl + pbase) = lo;

    hi.x = packsplit2(v8[0], v8[1], lo.x);
    hi.y = packsplit2(v8[2], v8[3], lo.y);
    hi.z = packsplit2(v8[4], v8[5], lo.z);
    hi.w = packsplit2(v8[6], v8[7], lo.w);
    *(uint4*)(Vh + pbase) = hi; *(uint4*)(Vl + pbase) = lo;
}

// ===========================================================================
// Causal flash attention v2: pre-converted bf16 planes, cp.async loads,
// double-buffered K/V stages, 3 barriers per tile.
// 8 warps: wm = warp&3 (16 q-rows); wn = warp>>2 (32-col S slice / 64-dim O).
// ===========================================================================
#define F2_QH   0
#define F2_QL   16384
#define F2_KV0  32768          // per stage: Kh | Kl | Vh | Vl, 16KB each
#define F2_STG  65536
#define F2_PH   163840
#define F2_PL   172032
#define F2_MX   180224
#define F2_RS   180736
#define F2_SMEM 181248

// A-fragment x4 address (row-major operand)
__device__ __forceinline__ uint32_t a_addr(uint32_t plane, int rowbase,
                                           int chbase, int lane, int rowbytes) {
    int m  = lane >> 3;
    int r  = rowbase + ((m & 1) << 3) + (lane & 7);
    int ch = chbase + (m >> 1);
    return plane + (uint32_t)(r * rowbytes + ((ch ^ (r & 7)) << 4));
}
// B-fragment x4 address (col-major consumption of K rows)
__device__ __forceinline__ uint32_t b_addr(uint32_t plane, int rowbase,
                                           int chbase, int lane, int rowbytes) {
    int m  = lane >> 3;
    int r  = rowbase + ((m >> 1) << 3) + (lane & 7);
    int ch = chbase + (m & 1);
    return plane + (uint32_t)(r * rowbytes + ((ch ^ (r & 7)) << 4));
}

__global__ __launch_bounds__(256, 1)
void flash_attn_mma2_kernel(const uint8_t* __restrict__ Qh, const uint8_t* __restrict__ Ql,
                            const uint8_t* __restrict__ Kh, const uint8_t* __restrict__ Kl,
                            const uint8_t* __restrict__ Vh, const uint8_t* __restrict__ Vl,
                            float* __restrict__ O)
{
    extern __shared__ char smem[];
    const uint32_t su = smem_to_u32(smem);
    float* smx = (float*)(smem + F2_MX);
    float* srs = (float*)(smem + F2_RS);

    const int tid  = threadIdx.x;
    const int lane = tid & 31;
    const int warp = tid >> 5;
    const int wm   = warp & 3;
    const int wn   = warp >> 2;
    const int qt   = (int)gridDim.x - 1 - (int)blockIdx.x;
    const int h    = blockIdx.y;
    const int b    = blockIdx.z;
    const int q0   = qt * 64;

    const size_t hb = (size_t)(b * NHEADS + h) * 32;   // tile index base

    // ---- prologue: async copy Q tile + K0/V0 ----
    {
        size_t qoff = (hb + qt) * 16384;
#pragma unroll
        for (int j = 0; j < 4; ++j) {
            uint32_t o = (uint32_t)((tid + j * 256) * 16);
            cp16(su + F2_QH + o, Qh + qoff + o);
            cp16(su + F2_QL + o, Ql + qoff + o);
        }
        size_t koff = (hb + 0) * 16384;
#pragma unroll
        for (int j = 0; j < 4; ++j) {
            uint32_t o = (uint32_t)((tid + j * 256) * 16);
            cp16(su + F2_KV0 + o,         Kh + koff + o);
            cp16(su + F2_KV0 + 16384 + o, Kl + koff + o);
            cp16(su + F2_KV0 + 32768 + o, Vh + koff + o);
            cp16(su + F2_KV0 + 49152 + o, Vl + koff + o);
        }
        CP_COMMIT();
    }

    const int r_lo = lane >> 2;
    const int pr0  = wm * 16 + r_lo;
    const int pr1  = pr0 + 8;
    float m0 = -1e30f, m1 = -1e30f, l0 = 0.0f, l1 = 0.0f;
    float acc[8][4];
#pragma unroll
    for (int ng = 0; ng < 8; ++ng)
#pragma unroll
        for (int q = 0; q < 4; ++q)
            acc[ng][q] = 0.0f;

    for (int kt = 0; kt <= qt; ++kt) {
        const int k0 = kt * 64;
        const uint32_t kvb = su + F2_KV0 + (uint32_t)(kt & 1) * F2_STG;

        CP_WAIT0();
        __syncthreads();   // (1) stage data + prev-iter smem reads settled

        // prefetch next K/V into the other stage
        if (kt < qt) {
            const uint32_t nb = su + F2_KV0 + (uint32_t)((kt + 1) & 1) * F2_STG;
            size_t koff = (hb + (kt + 1)) * 16384;
#pragma unroll
            for (int j = 0; j < 4; ++j) {
                uint32_t o = (uint32_t)((tid + j * 256) * 16);
                cp16(nb + o,         Kh + koff + o);
                cp16(nb + 16384 + o, Kl + koff + o);
                cp16(nb + 32768 + o, Vh + koff + o);
                cp16(nb + 49152 + o, Vl + koff + o);
            }
            CP_COMMIT();
        }

        // ---- S = Q . K^T  (3-plane bf16 split) ----
        float sacc[4][4];
#pragma unroll
        for (int nf = 0; nf < 4; ++nf)
#pragma unroll
            for (int q = 0; q < 4; ++q)
                sacc[nf][q] = 0.0f;

#pragma unroll
        for (int ks = 0; ks < 8; ++ks) {
            uint32_t qh[4], ql[4];
            uint32_t qa = a_addr(su + F2_QH, wm * 16, ks * 2, lane, 256);
            LDSM_X4(qh[0], qh[1], qh[2], qh[3], qa);
            LDSM_X4(ql[0], ql[1], ql[2], ql[3], qa + 16384);
#pragma unroll
            for (int g = 0; g < 2; ++g) {
                uint32_t khf[4], klf[4];
                uint32_t ka = b_addr(kvb, wn * 32 + g * 16, ks * 2, lane, 256);
                LDSM_X4(khf[0], khf[1], khf[2], khf[3], ka);
                LDSM_X4(klf[0], klf[1], klf[2], klf[3], ka + 16384);
#pragma unroll
                for (int sub = 0; sub < 2; ++sub) {
                    float* d = sacc[g * 2 + sub];
                    MMA_BF16(d, qh, khf[2 * sub], khf[2 * sub + 1]);
                    MMA_BF16(d, qh, klf[2 * sub], klf[2 * sub + 1]);
                    MMA_BF16(d, ql, khf[2 * sub], khf[2 * sub + 1]);
                }
            }
        }

        // ---- causal mask (diagonal tile) ----
        if (kt == qt) {
#pragma unroll
            for (int nf = 0; nf < 4; ++nf)
#pragma unroll
                for (int j = 0; j < 4; ++j) {
                    int rw = q0 + wm * 16 + r_lo + ((j >> 1) << 3);
                    int cl = k0 + wn * 32 + nf * 8 + 2 * (lane & 3) + (j & 1);
                    if (cl > rw) sacc[nf][j] = -1e30f;
                }
        }

        // ---- local (half-row) max ----
        float mx0 = -1e30f, mx1 = -1e30f;
#pragma unroll
        for (int nf = 0; nf < 4; ++nf) {
            mx0 = fmaxf(mx0, fmaxf(sacc[nf][0], sacc[nf][1]));
            mx1 = fmaxf(mx1, fmaxf(sacc[nf][2], sacc[nf][3]));
        }
        mx0 = fmaxf(mx0, __shfl_xor_sync(0xFFFFFFFFu, mx0, 1));
        mx0 = fmaxf(mx0, __shfl_xor_sync(0xFFFFFFFFu, mx0, 2));
        mx1 = fmaxf(mx1, __shfl_xor_sync(0xFFFFFFFFu, mx1, 1));
        mx1 = fmaxf(mx1, __shfl_xor_sync(0xFFFFFFFFu, mx1, 2));
        if ((lane & 3) == 0) {
            smx[wn * 64 + pr0] = mx0;
            smx[wn * 64 + pr1] = mx1;
        }
        __syncthreads();   // (2) maxima visible

        float mn0 = fmaxf(m0, fmaxf(smx[pr0], smx[64 + pr0]));
        float mn1 = fmaxf(m1, fmaxf(smx[pr1], smx[64 + pr1]));
        float al0 = __expf(m0 - mn0), al1 = __expf(m1 - mn1);
        m0 = mn0; m1 = mn1;

        // ---- p = exp(s-m), store P planes, half-row sums ----
        float rs0 = 0.0f, rs1 = 0.0f;
#pragma unroll
        for (int nf = 0; nf < 4; ++nf) {
            float p00 = __expf(sacc[nf][0] - mn0);
            float p01 = __expf(sacc[nf][1] - mn0);
            float p10 = __expf(sacc[nf][2] - mn1);
            float p11 = __expf(sacc[nf][3] - mn1);
            rs0 += p00 + p01;
            rs1 += p10 + p11;
            int pch = wn * 4 + nf;
            uint32_t lo, hi;
            hi = packsplit2(p00, p01, lo);
            uint32_t off0 = (uint32_t)(pr0 * 128 + ((pch ^ (pr0 & 7)) << 4) + 4 * (lane & 3));
            *(uint32_t*)(smem + F2_PH + off0) = hi;
            *(uint32_t*)(smem + F2_PL + off0) = lo;
            hi = packsplit2(p10, p11, lo);
            uint32_t off1 = (uint32_t)(pr1 * 128 + ((pch ^ (pr1 & 7)) << 4) + 4 * (lane & 3));
            *(uint32_t*)(smem + F2_PH + off1) = hi;
            *(uint32_t*)(smem + F2_PL + off1) = lo;
        }
        rs0 += __shfl_xor_sync(0xFFFFFFFFu, rs0, 1);
        rs0 += __shfl_xor_sync(0xFFFFFFFFu, rs0, 2);
        rs1 += __shfl_xor_sync(0xFFFFFFFFu, rs1, 1);
        rs1 += __shfl_xor_sync(0xFFFFFFFFu, rs1, 2);
        if ((lane & 3) == 0) {
            srs[wn * 64 + pr0] = rs0;
            srs[wn * 64 + pr1] = rs1;
        }

#pragma unroll
        for (int ng = 0; ng < 8; ++ng) {
            acc[ng][0] *= al0; acc[ng][1] *= al0;
            acc[ng][2] *= al1; acc[ng][3] *= al1;
        }

        __syncthreads();   // (3) P, rs visible

        l0 = l0 * al0 + srs[pr0] + srs[64 + pr0];
        l1 = l1 * al1 + srs[pr1] + srs[64 + pr1];

        // ---- O += P . V  (3-plane; V via ldmatrix.trans) ----
        const uint32_t vb = kvb + 32768;
#pragma unroll
        for (int t = 0; t < 4; ++t) {
            uint32_t ph[4], pl[4];
            uint32_t pa = a_addr(su + F2_PH, wm * 16, t * 2, lane, 128);
            LDSM_X4(ph[0], ph[1], ph[2], ph[3], pa);
            LDSM_X4(pl[0], pl[1], pl[2], pl[3], pa + (F2_PL - F2_PH));
#pragma unroll
            for (int ng = 0; ng < 8; ng += 2) {
                uint32_t vh[4], vl[4];
                uint32_t va = a_addr(vb, t * 16, wn * 8 + ng, lane, 256);
                LDSM_X4_T(vh[0], vh[1], vh[2], vh[3], va);
                LDSM_X4_T(vl[0], vl[1], vl[2], vl[3], va + 16384);
                MMA_BF16(acc[ng],     ph, vh[0], vh[1]);
                MMA_BF16(acc[ng],     ph, vl[0], vl[1]);
                MMA_BF16(acc[ng],     pl, vh[0], vh[1]);
                MMA_BF16(acc[ng + 1], ph, vh[2], vh[3]);
                MMA_BF16(acc[ng + 1], ph, vl[2], vl[3]);
                MMA_BF16(acc[ng + 1], pl, vh[2], vh[3]);
            }
        }
    }

    // ---- finalize ----
    float* Ob = O + (size_t)(b * SEQ) * DMODEL + h * DHEAD;
    float inv0 = 1.0f / l0, inv1 = 1.0f / l1;
    int row0 = q0 + wm * 16 + r_lo;
#pragma unroll
    for (int ng = 0; ng < 8; ++ng) {
        int col = wn * 64 + ng * 8 + 2 * (lane & 3);
        *(float2*)&Ob[(size_t)row0 * DMODEL + col] =
            make_float2(acc[ng][0] * inv0, acc[ng][1] * inv0);
        *(float2*)&Ob[(size_t)(row0 + 8) * DMODEL + col] =
            make_float2(acc[ng][2] * inv1, acc[ng][3] * inv1);
    }
}

// ---------------------------------------------------------------------------
// kernel_launch
// Inputs (metadata order): x, cos, sin, Wq, Wk, Wv, Wo  (all fp32)
// Output: (B, S, D_MODEL) fp32
// ---------------------------------------------------------------------------
extern "C" void kernel_launch(void* const* d_in, const int* in_sizes, int n_in,
                              void* d_out, int out_size)
{
    const float* x    = (const float*)d_in[0];
    const float* cosT = (const float*)d_in[1];
    const float* sinT = (const float*)d_in[2];
    const float* Wq   = (const float*)d_in[3];
    const float* Wk   = (const float*)d_in[4];
    const float* Wv   = (const float*)d_in[5];
    const float* Wo   = (const float*)d_in[6];
    float* out = (float*)d_out;

    float *qp, *kp, *vp, *cp;
    uint8_t *qh, *ql, *kh, *kl, *vh, *vl;
    cudaGetSymbolAddress((void**)&qp, g_Q);
    cudaGetSymbolAddress((void**)&kp, g_K);
    cudaGetSymbolAddress((void**)&vp, g_V);
    cudaGetSymbolAddress((void**)&cp, g_C);
    cudaGetSymbolAddress((void**)&qh, g_Qh);
    cudaGetSymbolAddress((void**)&ql, g_Ql);
    cudaGetSymbolAddress((void**)&kh, g_Kh);
    cudaGetSymbolAddress((void**)&kl, g_Kl);
    cudaGetSymbolAddress((void**)&vh, g_Vh);
    cudaGetSymbolAddress((void**)&vl, g_Vl);

    cudaFuncSetAttribute(gemm_mma_kernel,
                         cudaFuncAttributeMaxDynamicSharedMemorySize, MM_SMEM);
    cudaFuncSetAttribute(flash_attn_mma2_kernel,
                         cudaFuncAttributeMaxDynamicSharedMemorySize, F2_SMEM);

    dim3 ggrid(DMODEL / MM_BN, NTOK / MM_BM);   // (16, 32)

    // QKV projections (mma.sync bf16 x2-split)
    gemm_mma_kernel<<<ggrid, 256, MM_SMEM>>>(x, Wq, qp, NTOK, DMODEL, DMODEL);
    gemm_mma_kernel<<<ggrid, 256, MM_SMEM>>>(x, Wk, kp, NTOK, DMODEL, DMODEL);
    gemm_mma_kernel<<<ggrid, 256, MM_SMEM>>>(x, Wv, vp, NTOK, DMODEL, DMODEL);

    // RoPE + bf16 plane conversion (Q scaled)
    int cvt_threads = NTOK * NHEADS * 16;
    rope_convert_kernel<<<(cvt_threads + 255) / 256, 256>>>(
        qp, kp, vp, cosT, sinT, qh, ql, kh, kl, vh, vl);

    // Causal flash attention (tensor cores, async-pipelined)
    dim3 fgrid(SEQ / 64, NHEADS, BATCH);   // (32, 16, 2)
    flash_attn_mma2_kernel<<<fgrid, 256, F2_SMEM>>>(qh, ql, kh, kl, vh, vl, cp);

    // Output projection -> d_out
    gemm_mma_kernel<<<ggrid, 256, MM_SMEM>>>(cp, Wo, out, NTOK, DMODEL, DMODEL);
}

// round 15
// speedup vs baseline: 2.1740x; 1.2538x over previous
#include <cuda_runtime.h>
#include <cuda_bf16.h>
#include <stdint.h>
#include <math.h>

// Problem constants
#define BATCH   2
#define SEQ     2048
#define DMODEL  2048
#define NHEADS  16
#define DHEAD   128
#define NTOK    (BATCH * SEQ)        // 4096 tokens
#define QSCALE  0.08838834764831845f // 1/sqrt(128)

// ---------------------------------------------------------------------------
// Scratch buffers (static device globals; no runtime allocation allowed)
// ---------------------------------------------------------------------------
__device__ float g_Q[(size_t)NTOK * DMODEL];
__device__ float g_K[(size_t)NTOK * DMODEL];
__device__ float g_V[(size_t)NTOK * DMODEL];
__device__ float g_C[(size_t)NTOK * DMODEL];
// FA planes (pre-swizzled tile layout, from R13)
#define PLANE_BYTES ((size_t)NTOK * DMODEL * 2)
__device__ uint8_t g_Qh[PLANE_BYTES], g_Ql[PLANE_BYTES];
__device__ uint8_t g_Kh[PLANE_BYTES], g_Kl[PLANE_BYTES];
__device__ uint8_t g_Vh[PLANE_BYTES], g_Vl[PLANE_BYTES];
// GEMM planes (row-major bf16 hi/lo)
__device__ uint8_t g_Xh[PLANE_BYTES],  g_Xl[PLANE_BYTES];    // x (4096x2048)
__device__ uint8_t g_Ch[PLANE_BYTES],  g_Cl[PLANE_BYTES];    // context
#define WPLANE_BYTES ((size_t)DMODEL * DMODEL * 2)
__device__ uint8_t g_Wqh[WPLANE_BYTES], g_Wql[WPLANE_BYTES];
__device__ uint8_t g_Wkh[WPLANE_BYTES], g_Wkl[WPLANE_BYTES];
__device__ uint8_t g_Wvh[WPLANE_BYTES], g_Wvl[WPLANE_BYTES];
__device__ uint8_t g_Woh[WPLANE_BYTES], g_Wol[WPLANE_BYTES];

// ===========================================================================
// Helpers
// ===========================================================================
__device__ __forceinline__ uint32_t smem_to_u32(const void* p) {
    uint32_t a;
    asm("{ .reg .u64 t; cvta.to.shared.u64 t, %1; cvt.u32.u64 %0, t; }"
        : "=r"(a) : "l"(p));
    return a;
}

#define LDSM_X4(r0, r1, r2, r3, addr) \
    asm volatile("ldmatrix.sync.aligned.m8n8.x4.shared.b16 {%0,%1,%2,%3}, [%4];" \
                 : "=r"(r0), "=r"(r1), "=r"(r2), "=r"(r3) : "r"(addr))

#define LDSM_X4_T(r0, r1, r2, r3, addr) \
    asm volatile("ldmatrix.sync.aligned.m8n8.x4.trans.shared.b16 {%0,%1,%2,%3}, [%4];" \
                 : "=r"(r0), "=r"(r1), "=r"(r2), "=r"(r3) : "r"(addr))

#define MMA_BF16(d, a, b0, b1) \
    asm volatile("mma.sync.aligned.m16n8k16.row.col.f32.bf16.bf16.f32 " \
                 "{%0,%1,%2,%3}, {%4,%5,%6,%7}, {%8,%9}, {%0,%1,%2,%3};" \
                 : "+f"((d)[0]), "+f"((d)[1]), "+f"((d)[2]), "+f"((d)[3]) \
                 : "r"((a)[0]), "r"((a)[1]), "r"((a)[2]), "r"((a)[3]), \
                   "r"(b0), "r"(b1))

__device__ __forceinline__ void cp16(uint32_t dst, const void* src) {
    asm volatile("cp.async.cg.shared.global [%0], [%1], 16;"
                 :: "r"(dst), "l"(src));
}
#define CP_COMMIT() asm volatile("cp.async.commit_group;" ::: "memory")
#define CP_WAIT0()  asm volatile("cp.async.wait_group 0;" ::: "memory")
#define CP_WAIT1()  asm volatile("cp.async.wait_group 1;" ::: "memory")

// Split two floats into packed bf16 hi pair (low half = first arg) + lo pair.
__device__ __forceinline__ uint32_t packsplit2(float a, float b, uint32_t& lo_out) {
    __nv_bfloat16 ha = __float2bfloat16_rn(a);
    __nv_bfloat16 hb = __float2bfloat16_rn(b);
    float la = a - __bfloat162float(ha);
    float lb = b - __bfloat162float(hb);
    __nv_bfloat16 hla = __float2bfloat16_rn(la);
    __nv_bfloat16 hlb = __float2bfloat16_rn(lb);
    lo_out = ((uint32_t)__bfloat16_as_ushort(hlb) << 16) |
             (uint32_t)__bfloat16_as_ushort(hla);
    return ((uint32_t)__bfloat16_as_ushort(hb) << 16) |
           (uint32_t)__bfloat16_as_ushort(ha);
}

// ===========================================================================
// split_planes: fp32 row-major -> bf16 hi/lo planes (row-major, same order).
// One thread per 8 elements.
// ===========================================================================
__global__ void split_planes_kernel(const float* __restrict__ X,
                                    uint8_t* __restrict__ H,
                                    uint8_t* __restrict__ L,
                                    int total /* elements/8 */)
{
    int i = blockIdx.x * blockDim.x + threadIdx.x;
    if (i >= total) return;
    const float* src = X + (size_t)i * 8;
    float4 v0 = *(const float4*)src;
    float4 v1 = *(const float4*)(src + 4);
    uint4 hi, lo;
    hi.x = packsplit2(v0.x, v0.y, lo.x);
    hi.y = packsplit2(v0.z, v0.w, lo.y);
    hi.z = packsplit2(v1.x, v1.y, lo.z);
    hi.w = packsplit2(v1.z, v1.w, lo.w);
    *(uint4*)(H + (size_t)i * 16) = hi;
    *(uint4*)(L + (size_t)i * 16) = lo;
}

// ===========================================================================
// Tensor-core GEMM v2: pre-split bf16 planes, cp.async 3-stage pipeline.
// Y[M,N] = A[M,K] @ B[N,K]^T  (A = Xhi+Xlo, B = Whi+Wlo, 3-term product).
// Block 128x128, BK=32, 8 warps (wm=warp&3: 32 rows, wn=warp>>2: 64 cols).
// 1 barrier per chunk; occupancy 2.
// ===========================================================================
#define MM_AHI 0
#define MM_ALO 8192
#define MM_BHI 16384
#define MM_BLO 24576
#define MM_STAGE 32768
#define G2_SMEM (3 * MM_STAGE)     // 98304 bytes

__device__ __forceinline__ uint32_t sw_off(int row, int ch) {
    return (uint32_t)(row * 64 + ((ch ^ ((row >> 1) & 3)) << 4));
}

__global__ __launch_bounds__(256, 2)
void gemm_mma2_kernel(const uint8_t* __restrict__ Ah, const uint8_t* __restrict__ Al,
                      const uint8_t* __restrict__ Bh, const uint8_t* __restrict__ Bl,
                      float* __restrict__ Y, int M, int N, int K)
{
    extern __shared__ char smem[];
    const uint32_t su = smem_to_u32(smem);

    const int tid  = threadIdx.x;
    const int lane = tid & 31;
    const int warp = tid >> 5;
    const int wm   = warp & 3;
    const int wn   = warp >> 2;
    const int bm   = blockIdx.y * 128;
    const int bn   = blockIdx.x * 128;
    const int nchunk = K / 32;
    const size_t rowb = (size_t)K * 2;   // plane row stride in bytes

    // stage-issue: 2 cp16 per plane per thread (512 chunks of 16B per plane)
#define G2_ISSUE(c) do {                                                      \
        uint32_t sb = su + (uint32_t)((c) % 3) * MM_STAGE;                    \
        uint32_t cko = (uint32_t)(c) * 64;                                    \
        _Pragma("unroll")                                                     \
        for (int u = 0; u < 2; ++u) {                                         \
            int f = tid * 2 + u;                                              \
            int row = f >> 2, ch = f & 3;                                     \
            uint32_t so = sw_off(row, ch);                                    \
            size_t ga = (size_t)(bm + row) * rowb + cko + ch * 16;            \
            cp16(sb + MM_AHI + so, Ah + ga);                                  \
            cp16(sb + MM_ALO + so, Al + ga);                                  \
            size_t gb = (size_t)(bn + row) * rowb + cko + ch * 16;            \
            cp16(sb + MM_BHI + so, Bh + gb);                                  \
            cp16(sb + MM_BLO + so, Bl + gb);                                  \
        }                                                                     \
        CP_COMMIT();                                                          \
    } while (0)

    G2_ISSUE(0);
    G2_ISSUE(1);

    float acc[2][8][4];
#pragma unroll
    for (int mf = 0; mf < 2; ++mf)
#pragma unroll
        for (int nf = 0; nf < 8; ++nf)
#pragma unroll
            for (int q = 0; q < 4; ++q)
                acc[mf][nf][q] = 0.0f;

    for (int c = 0; c < nchunk; ++c) {
        if (c == nchunk - 1) { CP_WAIT0(); } else { CP_WAIT1(); }
        __syncthreads();

        if (c + 2 < nchunk) G2_ISSUE(c + 2);

        const uint32_t sb   = su + (uint32_t)(c % 3) * MM_STAGE;
        const uint32_t sAhi = sb + MM_AHI;
        const uint32_t sAlo = sb + MM_ALO;
        const uint32_t sBhi = sb + MM_BHI;
        const uint32_t sBlo = sb + MM_BLO;

#pragma unroll
        for (int ks = 0; ks < 2; ++ks) {
            uint32_t ah[2][4], al[2][4];
#pragma unroll
            for (int mf = 0; mf < 2; ++mf) {
                int row = wm * 32 + mf * 16 + (lane & 15);
                int ch  = ks * 2 + (lane >> 4);
                uint32_t off = sw_off(row, ch);
                LDSM_X4(ah[mf][0], ah[mf][1], ah[mf][2], ah[mf][3], sAhi + off);
                LDSM_X4(al[mf][0], al[mf][1], al[mf][2], al[mf][3], sAlo + off);
            }
#pragma unroll
            for (int nf2 = 0; nf2 < 4; ++nf2) {
                uint32_t bh[4], bl[4];
                int row = wn * 64 + nf2 * 16 + (lane & 15);
                int ch  = ks * 2 + (lane >> 4);
                uint32_t off = sw_off(row, ch);
                LDSM_X4(bh[0], bh[1], bh[2], bh[3], sBhi + off);
                LDSM_X4(bl[0], bl[1], bl[2], bl[3], sBlo + off);
#pragma unroll
                for (int mf = 0; mf < 2; ++mf)
#pragma unroll
                    for (int sub = 0; sub < 2; ++sub) {
                        float* d = acc[mf][nf2 * 2 + sub];
                        MMA_BF16(d, ah[mf], bh[sub], bh[sub + 2]);
                        MMA_BF16(d, ah[mf], bl[sub], bl[sub + 2]);
                        MMA_BF16(d, al[mf], bh[sub], bh[sub + 2]);
                    }
            }
        }
    }

#pragma unroll
    for (int mf = 0; mf < 2; ++mf) {
        int r0 = bm + wm * 32 + mf * 16 + (lane >> 2);
#pragma unroll
        for (int nf = 0; nf < 8; ++nf) {
            int col = bn + wn * 64 + nf * 8 + (lane & 3) * 2;
            float2 v0 = make_float2(acc[mf][nf][0], acc[mf][nf][1]);
            float2 v1 = make_float2(acc[mf][nf][2], acc[mf][nf][3]);
            *(float2*)&Y[(size_t)r0 * N + col]       = v0;
            *(float2*)&Y[(size_t)(r0 + 8) * N + col] = v1;
        }
    }
}

// ===========================================================================
// RoPE + FA-plane conversion (unchanged from R13 — proven)
// ===========================================================================
__global__ void rope_convert_kernel(const float* __restrict__ Q,
                                    const float* __restrict__ K,
                                    const float* __restrict__ V,
                                    const float* __restrict__ cosT,
                                    const float* __restrict__ sinT,
                                    uint8_t* __restrict__ Qh, uint8_t* __restrict__ Ql,
                                    uint8_t* __restrict__ Kh, uint8_t* __restrict__ Kl,
                                    uint8_t* __restrict__ Vh, uint8_t* __restrict__ Vl)
{
    int i = blockIdx.x * blockDim.x + threadIdx.x;
    if (i >= NTOK * NHEADS * 16) return;
    int ch    = i & 15;
    int h     = (i >> 4) & (NHEADS - 1);
    int token = i >> 8;
    int s     = token & (SEQ - 1);
    int b     = token >> 11;
    int d0    = ch * 8;
    int r     = s & 63;
    int tile  = s >> 6;

    size_t pbase = ((((size_t)(b * NHEADS + h)) * 32 + tile) * 64 + r) * 256
                 + (uint32_t)((ch ^ (r & 7)) << 4);

    const float* xq = Q + (size_t)token * DMODEL + h * DHEAD;
    const float* xk = K + (size_t)token * DMODEL + h * DHEAD;
    const float* xv = V + (size_t)token * DMODEL + h * DHEAD;

    float q8[8], k8[8], v8[8];
#pragma unroll
    for (int j = 0; j < 8; ++j) {
        int d = d0 + j;
        float c  = cosT[s * DHEAD + d];
        float sn = sinT[s * DHEAD + d];
        int   p  = (d < 64) ? d + 64 : d - 64;
        float sg = (d < 64) ? -1.0f : 1.0f;
        q8[j] = (xq[d] * c + sg * xq[p] * sn) * QSCALE;
        k8[j] =  xk[d] * c + sg * xk[p] * sn;
        v8[j] =  xv[d];
    }

    uint4 hi, lo;
    hi.x = packsplit2(q8[0], q8[1], lo.x);
    hi.y = packsplit2(q8[2], q8[3], lo.y);
    hi.z = packsplit2(q8[4], q8[5], lo.z);
    hi.w = packsplit2(q8[6], q8[7], lo.w);
    *(uint4*)(Qh + pbase) = hi; *(uint4*)(Ql + pbase) = lo;

    hi.x = packsplit2(k8[0], k8[1], lo.x);
    hi.y = packsplit2(k8[2], k8[3], lo.y);
    hi.z = packsplit2(k8[4], k8[5], lo.z);
    hi.w = packsplit2(k8[6], k8[7], lo.w);
    *(uint4*)(Kh + pbase) = hi; *(uint4*)(Kl + pbase) = lo;

    hi.x = packsplit2(v8[0], v8[1], lo.x);
    hi.y = packsplit2(v8[2], v8[3], lo.y);
    hi.z = packsplit2(v8[4], v8[5], lo.z);
    hi.w = packsplit2(v8[6], v8[7], lo.w);
    *(uint4*)(Vh + pbase) = hi; *(uint4*)(Vl + pbase) = lo;
}

// ===========================================================================
// Causal flash attention v2 (unchanged from R13 — proven: 2411us total)
// ===========================================================================
#define F2_QH   0
#define F2_QL   16384
#define F2_KV0  32768
#define F2_STG  65536
#define F2_PH   163840
#define F2_PL   172032
#define F2_MX   180224
#define F2_RS   180736
#define F2_SMEM 181248

__device__ __forceinline__ uint32_t a_addr(uint32_t plane, int rowbase,
                                           int chbase, int lane, int rowbytes) {
    int m  = lane >> 3;
    int r  = rowbase + ((m & 1) << 3) + (lane & 7);
    int ch = chbase + (m >> 1);
    return plane + (uint32_t)(r * rowbytes + ((ch ^ (r & 7)) << 4));
}
__device__ __forceinline__ uint32_t b_addr(uint32_t plane, int rowbase,
                                           int chbase, int lane, int rowbytes) {
    int m  = lane >> 3;
    int r  = rowbase + ((m >> 1) << 3) + (lane & 7);
    int ch = chbase + (m & 1);
    return plane + (uint32_t)(r * rowbytes + ((ch ^ (r & 7)) << 4));
}

__global__ __launch_bounds__(256, 1)
void flash_attn_mma2_kernel(const uint8_t* __restrict__ Qh, const uint8_t* __restrict__ Ql,
                            const uint8_t* __restrict__ Kh, const uint8_t* __restrict__ Kl,
                            const uint8_t* __restrict__ Vh, const uint8_t* __restrict__ Vl,
                            float* __restrict__ O)
{
    extern __shared__ char smem[];
    const uint32_t su = smem_to_u32(smem);
    float* smx = (float*)(smem + F2_MX);
    float* srs = (float*)(smem + F2_RS);

    const int tid  = threadIdx.x;
    const int lane = tid & 31;
    const int warp = tid >> 5;
    const int wm   = warp & 3;
    const int wn   = warp >> 2;
    const int qt   = (int)gridDim.x - 1 - (int)blockIdx.x;
    const int h    = blockIdx.y;
    const int b    = blockIdx.z;
    const int q0   = qt * 64;

    const size_t hb = (size_t)(b * NHEADS + h) * 32;

    {
        size_t qoff = (hb + qt) * 16384;
#pragma unroll
        for (int j = 0; j < 4; ++j) {
            uint32_t o = (uint32_t)((tid + j * 256) * 16);
            cp16(su + F2_QH + o, Qh + qoff + o);
            cp16(su + F2_QL + o, Ql + qoff + o);
        }
        size_t koff = (hb + 0) * 16384;
#pragma unroll
        for (int j = 0; j < 4; ++j) {
            uint32_t o = (uint32_t)((tid + j * 256) * 16);
            cp16(su + F2_KV0 + o,         Kh + koff + o);
            cp16(su + F2_KV0 + 16384 + o, Kl + koff + o);
            cp16(su + F2_KV0 + 32768 + o, Vh + koff + o);
            cp16(su + F2_KV0 + 49152 + o, Vl + koff + o);
        }
        CP_COMMIT();
    }

    const int r_lo = lane >> 2;
    const int pr0  = wm * 16 + r_lo;
    const int pr1  = pr0 + 8;
    float m0 = -1e30f, m1 = -1e30f, l0 = 0.0f, l1 = 0.0f;
    float acc[8][4];
#pragma unroll
    for (int ng = 0; ng < 8; ++ng)
#pragma unroll
        for (int q = 0; q < 4; ++q)
            acc[ng][q] = 0.0f;

    for (int kt = 0; kt <= qt; ++kt) {
        const int k0 = kt * 64;
        const uint32_t kvb = su + F2_KV0 + (uint32_t)(kt & 1) * F2_STG;

        CP_WAIT0();
        __syncthreads();

        if (kt < qt) {
            const uint32_t nb = su + F2_KV0 + (uint32_t)((kt + 1) & 1) * F2_STG;
            size_t koff = (hb + (kt + 1)) * 16384;
#pragma unroll
            for (int j = 0; j < 4; ++j) {
                uint32_t o = (uint32_t)((tid + j * 256) * 16);
                cp16(nb + o,         Kh + koff + o);
                cp16(nb + 16384 + o, Kl + koff + o);
                cp16(nb + 32768 + o, Vh + koff + o);
                cp16(nb + 49152 + o, Vl + koff + o);
            }
            CP_COMMIT();
        }

        float sacc[4][4];
#pragma unroll
        for (int nf = 0; nf < 4; ++nf)
#pragma unroll
            for (int q = 0; q < 4; ++q)
                sacc[nf][q] = 0.0f;

#pragma unroll
        for (int ks = 0; ks < 8; ++ks) {
            uint32_t qh[4], ql[4];
            uint32_t qa = a_addr(su + F2_QH, wm * 16, ks * 2, lane, 256);
            LDSM_X4(qh[0], qh[1], qh[2], qh[3], qa);
            LDSM_X4(ql[0], ql[1], ql[2], ql[3], qa + 16384);
#pragma unroll
            for (int g = 0; g < 2; ++g) {
                uint32_t khf[4], klf[4];
                uint32_t ka = b_addr(kvb, wn * 32 + g * 16, ks * 2, lane, 256);
                LDSM_X4(khf[0], khf[1], khf[2], khf[3], ka);
                LDSM_X4(klf[0], klf[1], klf[2], klf[3], ka + 16384);
#pragma unroll
                for (int sub = 0; sub < 2; ++sub) {
                    float* d = sacc[g * 2 + sub];
                    MMA_BF16(d, qh, khf[2 * sub], khf[2 * sub + 1]);
                    MMA_BF16(d, qh, klf[2 * sub], klf[2 * sub + 1]);
                    MMA_BF16(d, ql, khf[2 * sub], khf[2 * sub + 1]);
                }
            }
        }

        if (kt == qt) {
#pragma unroll
            for (int nf = 0; nf < 4; ++nf)
#pragma unroll
                for (int j = 0; j < 4; ++j) {
                    int rw = q0 + wm * 16 + r_lo + ((j >> 1) << 3);
                    int cl = k0 + wn * 32 + nf * 8 + 2 * (lane & 3) + (j & 1);
                    if (cl > rw) sacc[nf][j] = -1e30f;
                }
        }

        float mx0 = -1e30f, mx1 = -1e30f;
#pragma unroll
        for (int nf = 0; nf < 4; ++nf) {
            mx0 = fmaxf(mx0, fmaxf(sacc[nf][0], sacc[nf][1]));
            mx1 = fmaxf(mx1, fmaxf(sacc[nf][2], sacc[nf][3]));
        }
        mx0 = fmaxf(mx0, __shfl_xor_sync(0xFFFFFFFFu, mx0, 1));
        mx0 = fmaxf(mx0, __shfl_xor_sync(0xFFFFFFFFu, mx0, 2));
        mx1 = fmaxf(mx1, __shfl_xor_sync(0xFFFFFFFFu, mx1, 1));
        mx1 = fmaxf(mx1, __shfl_xor_sync(0xFFFFFFFFu, mx1, 2));
        if ((lane & 3) == 0) {
            smx[wn * 64 + pr0] = mx0;
            smx[wn * 64 + pr1] = mx1;
        }
        __syncthreads();

        float mn0 = fmaxf(m0, fmaxf(smx[pr0], smx[64 + pr0]));
        float mn1 = fmaxf(m1, fmaxf(smx[pr1], smx[64 + pr1]));
        float al0 = __expf(m0 - mn0), al1 = __expf(m1 - mn1);
        m0 = mn0; m1 = mn1;

        float rs0 = 0.0f, rs1 = 0.0f;
#pragma unroll
        for (int nf = 0; nf < 4; ++nf) {
            float p00 = __expf(sacc[nf][0] - mn0);
            float p01 = __expf(sacc[nf][1] - mn0);
            float p10 = __expf(sacc[nf][2] - mn1);
            float p11 = __expf(sacc[nf][3] - mn1);
            rs0 += p00 + p01;
            rs1 += p10 + p11;
            int pch = wn * 4 + nf;
            uint32_t lo, hi;
            hi = packsplit2(p00, p01, lo);
            uint32_t off0 = (uint32_t)(pr0 * 128 + ((pch ^ (pr0 & 7)) << 4) + 4 * (lane & 3));
            *(uint32_t*)(smem + F2_PH + off0) = hi;
            *(uint32_t*)(smem + F2_PL + off0) = lo;
            hi = packsplit2(p10, p11, lo);
            uint32_t off1 = (uint32_t)(pr1 * 128 + ((pch ^ (pr1 & 7)) << 4) + 4 * (lane & 3));
            *(uint32_t*)(smem + F2_PH + off1) = hi;
            *(uint32_t*)(smem + F2_PL + off1) = lo;
        }
        rs0 += __shfl_xor_sync(0xFFFFFFFFu, rs0, 1);
        rs0 += __shfl_xor_sync(0xFFFFFFFFu, rs0, 2);
        rs1 += __shfl_xor_sync(0xFFFFFFFFu, rs1, 1);
        rs1 += __shfl_xor_sync(0xFFFFFFFFu, rs1, 2);
        if ((lane & 3) == 0) {
            srs[wn * 64 + pr0] = rs0;
            srs[wn * 64 + pr1] = rs1;
        }

#pragma unroll
        for (int ng = 0; ng < 8; ++ng) {
            acc[ng][0] *= al0; acc[ng][1] *= al0;
            acc[ng][2] *= al1; acc[ng][3] *= al1;
        }

        __syncthreads();

        l0 = l0 * al0 + srs[pr0] + srs[64 + pr0];
        l1 = l1 * al1 + srs[pr1] + srs[64 + pr1];

        const uint32_t vb = kvb + 32768;
#pragma unroll
        for (int t = 0; t < 4; ++t) {
            uint32_t ph[4], pl[4];
            uint32_t pa = a_addr(su + F2_PH, wm * 16, t * 2, lane, 128);
            LDSM_X4(ph[0], ph[1], ph[2], ph[3], pa);
            LDSM_X4(pl[0], pl[1], pl[2], pl[3], pa + (F2_PL - F2_PH));
#pragma unroll
            for (int ng = 0; ng < 8; ng += 2) {
                uint32_t vh[4], vl[4];
                uint32_t va = a_addr(vb, t * 16, wn * 8 + ng, lane, 256);
                LDSM_X4_T(vh[0], vh[1], vh[2], vh[3], va);
                LDSM_X4_T(vl[0], vl[1], vl[2], vl[3], va + 16384);
                MMA_BF16(acc[ng],     ph, vh[0], vh[1]);
                MMA_BF16(acc[ng],     ph, vl[0], vl[1]);
                MMA_BF16(acc[ng],     pl, vh[0], vh[1]);
                MMA_BF16(acc[ng + 1], ph, vh[2], vh[3]);
                MMA_BF16(acc[ng + 1], ph, vl[2], vl[3]);
                MMA_BF16(acc[ng + 1], pl, vh[2], vh[3]);
            }
        }
    }

    float* Ob = O + (size_t)(b * SEQ) * DMODEL + h * DHEAD;
    float inv0 = 1.0f / l0, inv1 = 1.0f / l1;
    int row0 = q0 + wm * 16 + r_lo;
#pragma unroll
    for (int ng = 0; ng < 8; ++ng) {
        int col = wn * 64 + ng * 8 + 2 * (lane & 3);
        *(float2*)&Ob[(size_t)row0 * DMODEL + col] =
            make_float2(acc[ng][0] * inv0, acc[ng][1] * inv0);
        *(float2*)&Ob[(size_t)(row0 + 8) * DMODEL + col] =
            make_float2(acc[ng][2] * inv1, acc[ng][3] * inv1);
    }
}

// ---------------------------------------------------------------------------
// kernel_launch
// Inputs (metadata order): x, cos, sin, Wq, Wk, Wv, Wo  (all fp32)
// Output: (B, S, D_MODEL) fp32
// ---------------------------------------------------------------------------
extern "C" void kernel_launch(void* const* d_in, const int* in_sizes, int n_in,
                              void* d_out, int out_size)
{
    const float* x    = (const float*)d_in[0];
    const float* cosT = (const float*)d_in[1];
    const float* sinT = (const float*)d_in[2];
    const float* Wq   = (const float*)d_in[3];
    const float* Wk   = (const float*)d_in[4];
    const float* Wv   = (const float*)d_in[5];
    const float* Wo   = (const float*)d_in[6];
    float* out = (float*)d_out;

    float *qp, *kp, *vp, *cp;
    uint8_t *qh, *ql, *kh, *kl, *vh, *vl;
    uint8_t *xh, *xl, *ch, *cl;
    uint8_t *wqh, *wql, *wkh, *wkl, *wvh, *wvl, *woh, *wol;
    cudaGetSymbolAddress((void**)&qp, g_Q);
    cudaGetSymbolAddress((void**)&kp, g_K);
    cudaGetSymbolAddress((void**)&vp, g_V);
    cudaGetSymbolAddress((void**)&cp, g_C);
    cudaGetSymbolAddress((void**)&qh, g_Qh);
    cudaGetSymbolAddress((void**)&ql, g_Ql);
    cudaGetSymbolAddress((void**)&kh, g_Kh);
    cudaGetSymbolAddress((void**)&kl, g_Kl);
    cudaGetSymbolAddress((void**)&vh, g_Vh);
    cudaGetSymbolAddress((void**)&vl, g_Vl);
    cudaGetSymbolAddress((void**)&xh, g_Xh);
    cudaGetSymbolAddress((void**)&xl, g_Xl);
    cudaGetSymbolAddress((void**)&ch, g_Ch);
    cudaGetSymbolAddress((void**)&cl, g_Cl);
    cudaGetSymbolAddress((void**)&wqh, g_Wqh);
    cudaGetSymbolAddress((void**)&wql, g_Wql);
    cudaGetSymbolAddress((void**)&wkh, g_Wkh);
    cudaGetSymbolAddress((void**)&wkl, g_Wkl);
    cudaGetSymbolAddress((void**)&wvh, g_Wvh);
    cudaGetSymbolAddress((void**)&wvl, g_Wvl);
    cudaGetSymbolAddress((void**)&woh, g_Woh);
    cudaGetSymbolAddress((void**)&wol, g_Wol);

    cudaFuncSetAttribute(gemm_mma2_kernel,
                         cudaFuncAttributeMaxDynamicSharedMemorySize, G2_SMEM);
    cudaFuncSetAttribute(flash_attn_mma2_kernel,
                         cudaFuncAttributeMaxDynamicSharedMemorySize, F2_SMEM);

    const int xq8 = NTOK * DMODEL / 8;     // x / C plane chunks
    const int wq8 = DMODEL * DMODEL / 8;   // weight plane chunks

    // Pre-split inputs to bf16 hi/lo planes
    split_planes_kernel<<<(xq8 + 255) / 256, 256>>>(x,  xh,  xl,  xq8);
    split_planes_kernel<<<(wq8 + 255) / 256, 256>>>(Wq, wqh, wql, wq8);
    split_planes_kernel<<<(wq8 + 255) / 256, 256>>>(Wk, wkh, wkl, wq8);
    split_planes_kernel<<<(wq8 + 255) / 256, 256>>>(Wv, wvh, wvl, wq8);
    split_planes_kernel<<<(wq8 + 255) / 256, 256>>>(Wo, woh, wol, wq8);

    dim3 ggrid(DMODEL / 128, NTOK / 128);   // (16, 32)

    // QKV projections
    gemm_mma2_kernel<<<ggrid, 256, G2_SMEM>>>(xh, xl, wqh, wql, qp, NTOK, DMODEL, DMODEL);
    gemm_mma2_kernel<<<ggrid, 256, G2_SMEM>>>(xh, xl, wkh, wkl, kp, NTOK, DMODEL, DMODEL);
    gemm_mma2_kernel<<<ggrid, 256, G2_SMEM>>>(xh, xl, wvh, wvl, vp, NTOK, DMODEL, DMODEL);

    // RoPE + FA plane conversion
    int cvt_threads = NTOK * NHEADS * 16;
    rope_convert_kernel<<<(cvt_threads + 255) / 256, 256>>>(
        qp, kp, vp, cosT, sinT, qh, ql, kh, kl, vh, vl);

    // Causal flash attention
    dim3 fgrid(SEQ / 64, NHEADS, BATCH);   // (32, 16, 2)
    flash_attn_mma2_kernel<<<fgrid, 256, F2_SMEM>>>(qh, ql, kh, kl, vh, vl, cp);

    // Output projection
    split_planes_kernel<<<(xq8 + 255) / 256, 256>>>(cp, ch, cl, xq8);
    gemm_mma2_kernel<<<ggrid, 256, G2_SMEM>>>(ch, cl, woh, wol, out, NTOK, DMODEL, DMODEL);
}

// round 17
// speedup vs baseline: 2.2099x; 1.0165x over previous
#include <cuda_runtime.h>
#include <cuda_bf16.h>
#include <stdint.h>
#include <math.h>

// Problem constants
#define BATCH   2
#define SEQ     2048
#define DMODEL  2048
#define NHEADS  16
#define DHEAD   128
#define NTOK    (BATCH * SEQ)        // 4096 tokens
#define QSCALE  0.08838834764831845f // 1/sqrt(128)

// ---------------------------------------------------------------------------
// Scratch buffers (static device globals; no runtime allocation allowed)
// ---------------------------------------------------------------------------
__device__ float g_Q[(size_t)NTOK * DMODEL];
__device__ float g_K[(size_t)NTOK * DMODEL];
__device__ float g_V[(size_t)NTOK * DMODEL];
// FA planes (pre-swizzled 64-row tile layout)
#define PLANE_BYTES ((size_t)NTOK * DMODEL * 2)
__device__ uint8_t g_Qh[PLANE_BYTES], g_Ql[PLANE_BYTES];
__device__ uint8_t g_Kh[PLANE_BYTES], g_Kl[PLANE_BYTES];
__device__ uint8_t g_Vh[PLANE_BYTES], g_Vl[PLANE_BYTES];
// GEMM planes (row-major bf16 hi/lo)
__device__ uint8_t g_Xh[PLANE_BYTES],  g_Xl[PLANE_BYTES];    // x (4096x2048)
__device__ uint8_t g_Ch[PLANE_BYTES],  g_Cl[PLANE_BYTES];    // context (written by FA)
#define WPLANE_BYTES ((size_t)DMODEL * DMODEL * 2)
__device__ uint8_t g_Wqh[WPLANE_BYTES], g_Wql[WPLANE_BYTES];
__device__ uint8_t g_Wkh[WPLANE_BYTES], g_Wkl[WPLANE_BYTES];
__device__ uint8_t g_Wvh[WPLANE_BYTES], g_Wvl[WPLANE_BYTES];
__device__ uint8_t g_Woh[WPLANE_BYTES], g_Wol[WPLANE_BYTES];

// ===========================================================================
// Helpers
// ===========================================================================
__device__ __forceinline__ uint32_t smem_to_u32(const void* p) {
    uint32_t a;
    asm("{ .reg .u64 t; cvta.to.shared.u64 t, %1; cvt.u32.u64 %0, t; }"
        : "=r"(a) : "l"(p));
    return a;
}

#define LDSM_X4(r0, r1, r2, r3, addr) \
    asm volatile("ldmatrix.sync.aligned.m8n8.x4.shared.b16 {%0,%1,%2,%3}, [%4];" \
                 : "=r"(r0), "=r"(r1), "=r"(r2), "=r"(r3) : "r"(addr))

#define LDSM_X4_T(r0, r1, r2, r3, addr) \
    asm volatile("ldmatrix.sync.aligned.m8n8.x4.trans.shared.b16 {%0,%1,%2,%3}, [%4];" \
                 : "=r"(r0), "=r"(r1), "=r"(r2), "=r"(r3) : "r"(addr))

#define MMA_BF16(d, a, b0, b1) \
    asm volatile("mma.sync.aligned.m16n8k16.row.col.f32.bf16.bf16.f32 " \
                 "{%0,%1,%2,%3}, {%4,%5,%6,%7}, {%8,%9}, {%0,%1,%2,%3};" \
                 : "+f"((d)[0]), "+f"((d)[1]), "+f"((d)[2]), "+f"((d)[3]) \
                 : "r"((a)[0]), "r"((a)[1]), "r"((a)[2]), "r"((a)[3]), \
                   "r"(b0), "r"(b1))

__device__ __forceinline__ void cp16(uint32_t dst, const void* src) {
    asm volatile("cp.async.cg.shared.global [%0], [%1], 16;"
                 :: "r"(dst), "l"(src));
}
#define CP_COMMIT() asm volatile("cp.async.commit_group;" ::: "memory")
#define CP_WAIT0()  asm volatile("cp.async.wait_group 0;" ::: "memory")
#define CP_WAIT1()  asm volatile("cp.async.wait_group 1;" ::: "memory")

// Split two floats into packed bf16 hi pair (low half = first arg) + lo pair.
__device__ __forceinline__ uint32_t packsplit2(float a, float b, uint32_t& lo_out) {
    __nv_bfloat16 ha = __float2bfloat16_rn(a);
    __nv_bfloat16 hb = __float2bfloat16_rn(b);
    float la = a - __bfloat162float(ha);
    float lb = b - __bfloat162float(hb);
    __nv_bfloat16 hla = __float2bfloat16_rn(la);
    __nv_bfloat16 hlb = __float2bfloat16_rn(lb);
    lo_out = ((uint32_t)__bfloat16_as_ushort(hlb) << 16) |
             (uint32_t)__bfloat16_as_ushort(hla);
    return ((uint32_t)__bfloat16_as_ushort(hb) << 16) |
           (uint32_t)__bfloat16_as_ushort(ha);
}

// ===========================================================================
// split_planes: fp32 row-major -> bf16 hi/lo planes (row-major, same order).
// ===========================================================================
__global__ void split_planes_kernel(const float* __restrict__ X,
                                    uint8_t* __restrict__ H,
                                    uint8_t* __restrict__ L,
                                    int total /* elements/8 */)
{
    int i = blockIdx.x * blockDim.x + threadIdx.x;
    if (i >= total) return;
    const float* src = X + (size_t)i * 8;
    float4 v0 = *(const float4*)src;
    float4 v1 = *(const float4*)(src + 4);
    uint4 hi, lo;
    hi.x = packsplit2(v0.x, v0.y, lo.x);
    hi.y = packsplit2(v0.z, v0.w, lo.y);
    hi.z = packsplit2(v1.x, v1.y, lo.z);
    hi.w = packsplit2(v1.z, v1.w, lo.w);
    *(uint4*)(H + (size_t)i * 16) = hi;
    *(uint4*)(L + (size_t)i * 16) = lo;
}

// ===========================================================================
// Tensor-core GEMM v2 (unchanged from R15 — at HMMA floor)
// ===========================================================================
#define MM_AHI 0
#define MM_ALO 8192
#define MM_BHI 16384
#define MM_BLO 24576
#define MM_STAGE 32768
#define G2_SMEM (3 * MM_STAGE)     // 98304 bytes

__device__ __forceinline__ uint32_t sw_off(int row, int ch) {
    return (uint32_t)(row * 64 + ((ch ^ ((row >> 1) & 3)) << 4));
}

__global__ __launch_bounds__(256, 2)
void gemm_mma2_kernel(const uint8_t* __restrict__ Ah, const uint8_t* __restrict__ Al,
                      const uint8_t* __restrict__ Bh, const uint8_t* __restrict__ Bl,
                      float* __restrict__ Y, int M, int N, int K)
{
    extern __shared__ char smem[];
    const uint32_t su = smem_to_u32(smem);

    const int tid  = threadIdx.x;
    const int lane = tid & 31;
    const int warp = tid >> 5;
    const int wm   = warp & 3;
    const int wn   = warp >> 2;
    const int bm   = blockIdx.y * 128;
    const int bn   = blockIdx.x * 128;
    const int nchunk = K / 32;
    const size_t rowb = (size_t)K * 2;

#define G2_ISSUE(c) do {                                                      \
        uint32_t sb = su + (uint32_t)((c) % 3) * MM_STAGE;                    \
        uint32_t cko = (uint32_t)(c) * 64;                                    \
        _Pragma("unroll")                                                     \
        for (int u = 0; u < 2; ++u) {                                         \
            int f = tid * 2 + u;                                              \
            int row = f >> 2, ch = f & 3;                                     \
            uint32_t so = sw_off(row, ch);                                    \
            size_t ga = (size_t)(bm + row) * rowb + cko + ch * 16;            \
            cp16(sb + MM_AHI + so, Ah + ga);                                  \
            cp16(sb + MM_ALO + so, Al + ga);                                  \
            size_t gb = (size_t)(bn + row) * rowb + cko + ch * 16;            \
            cp16(sb + MM_BHI + so, Bh + gb);                                  \
            cp16(sb + MM_BLO + so, Bl + gb);                                  \
        }                                                                     \
        CP_COMMIT();                                                          \
    } while (0)

    G2_ISSUE(0);
    G2_ISSUE(1);

    float acc[2][8][4];
#pragma unroll
    for (int mf = 0; mf < 2; ++mf)
#pragma unroll
        for (int nf = 0; nf < 8; ++nf)
#pragma unroll
            for (int q = 0; q < 4; ++q)
                acc[mf][nf][q] = 0.0f;

    for (int c = 0; c < nchunk; ++c) {
        if (c == nchunk - 1) { CP_WAIT0(); } else { CP_WAIT1(); }
        __syncthreads();

        if (c + 2 < nchunk) G2_ISSUE(c + 2);

        const uint32_t sb   = su + (uint32_t)(c % 3) * MM_STAGE;
        const uint32_t sAhi = sb + MM_AHI;
        const uint32_t sAlo = sb + MM_ALO;
        const uint32_t sBhi = sb + MM_BHI;
        const uint32_t sBlo = sb + MM_BLO;

#pragma unroll
        for (int ks = 0; ks < 2; ++ks) {
            uint32_t ah[2][4], al[2][4];
#pragma unroll
            for (int mf = 0; mf < 2; ++mf) {
                int row = wm * 32 + mf * 16 + (lane & 15);
                int ch  = ks * 2 + (lane >> 4);
                uint32_t off = sw_off(row, ch);
                LDSM_X4(ah[mf][0], ah[mf][1], ah[mf][2], ah[mf][3], sAhi + off);
                LDSM_X4(al[mf][0], al[mf][1], al[mf][2], al[mf][3], sAlo + off);
            }
#pragma unroll
            for (int nf2 = 0; nf2 < 4; ++nf2) {
                uint32_t bh[4], bl[4];
                int row = wn * 64 + nf2 * 16 + (lane & 15);
                int ch  = ks * 2 + (lane >> 4);
                uint32_t off = sw_off(row, ch);
                LDSM_X4(bh[0], bh[1], bh[2], bh[3], sBhi + off);
                LDSM_X4(bl[0], bl[1], bl[2], bl[3], sBlo + off);
#pragma unroll
                for (int mf = 0; mf < 2; ++mf)
#pragma unroll
                    for (int sub = 0; sub < 2; ++sub) {
                        float* d = acc[mf][nf2 * 2 + sub];
                        MMA_BF16(d, ah[mf], bh[sub], bh[sub + 2]);
                        MMA_BF16(d, ah[mf], bl[sub], bl[sub + 2]);
                        MMA_BF16(d, al[mf], bh[sub], bh[sub + 2]);
                    }
            }
        }
    }

#pragma unroll
    for (int mf = 0; mf < 2; ++mf) {
        int r0 = bm + wm * 32 + mf * 16 + (lane >> 2);
#pragma unroll
        for (int nf = 0; nf < 8; ++nf) {
            int col = bn + wn * 64 + nf * 8 + (lane & 3) * 2;
            float2 v0 = make_float2(acc[mf][nf][0], acc[mf][nf][1]);
            float2 v1 = make_float2(acc[mf][nf][2], acc[mf][nf][3]);
            *(float2*)&Y[(size_t)r0 * N + col]       = v0;
            *(float2*)&Y[(size_t)(r0 + 8) * N + col] = v1;
        }
    }
}

// ===========================================================================
// RoPE + FA-plane conversion (unchanged from R13 — proven)
// ===========================================================================
__global__ void rope_convert_kernel(const float* __restrict__ Q,
                                    const float* __restrict__ K,
                                    const float* __restrict__ V,
                                    const float* __restrict__ cosT,
                                    const float* __restrict__ sinT,
                                    uint8_t* __restrict__ Qh, uint8_t* __restrict__ Ql,
                                    uint8_t* __restrict__ Kh, uint8_t* __restrict__ Kl,
                                    uint8_t* __restrict__ Vh, uint8_t* __restrict__ Vl)
{
    int i = blockIdx.x * blockDim.x + threadIdx.x;
    if (i >= NTOK * NHEADS * 16) return;
    int ch    = i & 15;
    int h     = (i >> 4) & (NHEADS - 1);
    int token = i >> 8;
    int s     = token & (SEQ - 1);
    int b     = token >> 11;
    int d0    = ch * 8;
    int r     = s & 63;
    int tile  = s >> 6;

    size_t pbase = ((((size_t)(b * NHEADS + h)) * 32 + tile) * 64 + r) * 256
                 + (uint32_t)((ch ^ (r & 7)) << 4);

    const float* xq = Q + (size_t)token * DMODEL + h * DHEAD;
    const float* xk = K + (size_t)token * DMODEL + h * DHEAD;
    const float* xv = V + (size_t)token * DMODEL + h * DHEAD;

    float q8[8], k8[8], v8[8];
#pragma unroll
    for (int j = 0; j < 8; ++j) {
        int d = d0 + j;
        float c  = cosT[s * DHEAD + d];
        float sn = sinT[s * DHEAD + d];
        int   p  = (d < 64) ? d + 64 : d - 64;
        float sg = (d < 64) ? -1.0f : 1.0f;
        q8[j] = (xq[d] * c + sg * xq[p] * sn) * QSCALE;
        k8[j] =  xk[d] * c + sg * xk[p] * sn;
        v8[j] =  xv[d];
    }

    uint4 hi, lo;
    hi.x = packsplit2(q8[0], q8[1], lo.x);
    hi.y = packsplit2(q8[2], q8[3], lo.y);
    hi.z = packsplit2(q8[4], q8[5], lo.z);
    hi.w = packsplit2(q8[6], q8[7], lo.w);
    *(uint4*)(Qh + pbase) = hi; *(uint4*)(Ql + pbase) = lo;

    hi.x = packsplit2(k8[0], k8[1], lo.x);
    hi.y = packsplit2(k8[2], k8[3], lo.y);
    hi.z = packsplit2(k8[4], k8[5], lo.z);
    hi.w = packsplit2(k8[6], k8[7], lo.w);
    *(uint4*)(Kh + pbase) = hi; *(uint4*)(Kl + pbase) = lo;

    hi.x = packsplit2(v8[0], v8[1], lo.x);
    hi.y = packsplit2(v8[2], v8[3], lo.y);
    hi.z = packsplit2(v8[4], v8[5], lo.z);
    hi.w = packsplit2(v8[6], v8[7], lo.w);
    *(uint4*)(Vh + pbase) = hi; *(uint4*)(Vl + pbase) = lo;
}

// ===========================================================================
// Causal flash attention v3: 128-row q-tiles, warp owns 16 FULL rows.
// Softmax entirely warp-local (quad shuffles), 1 barrier per kv-tile.
// Writes context directly as bf16 hi/lo GEMM planes (row-major).
// ===========================================================================
#define F3_QH   0            // 128 x 256B (two 64-row tiles, contiguous)
#define F3_QL   32768
#define F3_KV0  65536        // stage: Kh | Kl | Vh | Vl, 16384 each
#define F3_STG  65536
#define F3_PH   196608       // P: 128 x 128B
#define F3_PL   212992
#define F3_SMEM 229376       // 224 KB

__device__ __forceinline__ uint32_t a_addr(uint32_t plane, int rowbase,
                                           int chbase, int lane, int rowbytes) {
    int m  = lane >> 3;
    int r  = rowbase + ((m & 1) << 3) + (lane & 7);
    int ch = chbase + (m >> 1);
    return plane + (uint32_t)(r * rowbytes + ((ch ^ (r & 7)) << 4));
}
__device__ __forceinline__ uint32_t b_addr(uint32_t plane, int rowbase,
                                           int chbase, int lane, int rowbytes) {
    int m  = lane >> 3;
    int r  = rowbase + ((m >> 1) << 3) + (lane & 7);
    int ch = chbase + (m & 1);
    return plane + (uint32_t)(r * rowbytes + ((ch ^ (r & 7)) << 4));
}

__global__ __launch_bounds__(256, 1)
void flash_attn_mma3_kernel(const uint8_t* __restrict__ Qh, const uint8_t* __restrict__ Ql,
                            const uint8_t* __restrict__ Kh, const uint8_t* __restrict__ Kl,
                            const uint8_t* __restrict__ Vh, const uint8_t* __restrict__ Vl,
                            uint8_t* __restrict__ Ch, uint8_t* __restrict__ Cl)
{
    extern __shared__ char smem[];
    const uint32_t su = smem_to_u32(smem);

    const int tid  = threadIdx.x;
    const int lane = tid & 31;
    const int warp = tid >> 5;           // 0..7, owns q-rows warp*16..+15
    const int qt   = (int)gridDim.x - 1 - (int)blockIdx.x;   // 0..15
    const int h    = blockIdx.y;
    const int b    = blockIdx.z;
    const int q0   = qt * 128;

    const size_t hb = (size_t)(b * NHEADS + h) * 32;   // 64-row tile base

    // ---- prologue: Q (two tiles = 32KB/plane) + K0/V0 stage ----
    {
        size_t qoff = (hb + 2 * qt) * 16384;
#pragma unroll
        for (int j = 0; j < 8; ++j) {
            uint32_t o = (uint32_t)((tid + j * 256) * 16);
            cp16(su + F3_QH + o, Qh + qoff + o);
            cp16(su + F3_QL + o, Ql + qoff + o);
        }
        size_t koff = hb * 16384;
#pragma unroll
        for (int j = 0; j < 4; ++j) {
            uint32_t o = (uint32_t)((tid + j * 256) * 16);
            cp16(su + F3_KV0 + o,         Kh + koff + o);
            cp16(su + F3_KV0 + 16384 + o, Kl + koff + o);
            cp16(su + F3_KV0 + 32768 + o, Vh + koff + o);
            cp16(su + F3_KV0 + 49152 + o, Vl + koff + o);
        }
        CP_COMMIT();
    }

    const int r_lo = lane >> 2;          // 0..7
    const int pr0  = warp * 16 + r_lo;   // local q-row (first half)
    const int pr1  = pr0 + 8;
    float m0 = -1e30f, m1 = -1e30f, l0 = 0.0f, l1 = 0.0f;
    float acc[16][4];
#pragma unroll
    for (int ng = 0; ng < 16; ++ng)
#pragma unroll
        for (int q = 0; q < 4; ++q)
            acc[ng][q] = 0.0f;

    const int nkv = 2 * qt + 2;
    for (int kt = 0; kt < nkv; ++kt) {
        const int k0 = kt * 64;
        const uint32_t kvb = su + F3_KV0 + (uint32_t)(kt & 1) * F3_STG;

        CP_WAIT0();
        __syncthreads();   // stage ready; prev-iter reads of other stage done

        if (kt + 1 < nkv) {
            const uint32_t nb = su + F3_KV0 + (uint32_t)((kt + 1) & 1) * F3_STG;
            size_t koff = (hb + (kt + 1)) * 16384;
#pragma unroll
            for (int j = 0; j < 4; ++j) {
                uint32_t o = (uint32_t)((tid + j * 256) * 16);
                cp16(nb + o,         Kh + koff + o);
                cp16(nb + 16384 + o, Kl + koff + o);
                cp16(nb + 32768 + o, Vh + koff + o);
                cp16(nb + 49152 + o, Vl + koff + o);
            }
            CP_COMMIT();
        }

        // ---- S = Q . K^T : warp computes S[16 x 64] ----
        float sacc[8][4];
#pragma unroll
        for (int nf = 0; nf < 8; ++nf)
#pragma unroll
            for (int q = 0; q < 4; ++q)
                sacc[nf][q] = 0.0f;

#pragma unroll
        for (int ks = 0; ks < 8; ++ks) {
            uint32_t qhf[4], qlf[4];
            uint32_t qa = a_addr(su + F3_QH, warp * 16, ks * 2, lane, 256);
            LDSM_X4(qhf[0], qhf[1], qhf[2], qhf[3], qa);
            LDSM_X4(qlf[0], qlf[1], qlf[2], qlf[3], qa + 32768);
#pragma unroll
            for (int g = 0; g < 4; ++g) {
                uint32_t khf[4], klf[4];
                uint32_t ka = b_addr(kvb, g * 16, ks * 2, lane, 256);
                LDSM_X4(khf[0], khf[1], khf[2], khf[3], ka);
                LDSM_X4(klf[0], klf[1], klf[2], klf[3], ka + 16384);
#pragma unroll
                for (int sub = 0; sub < 2; ++sub) {
                    float* d = sacc[g * 2 + sub];
                    MMA_BF16(d, qhf, khf[2 * sub], khf[2 * sub + 1]);
                    MMA_BF16(d, qhf, klf[2 * sub], klf[2 * sub + 1]);
                    MMA_BF16(d, qlf, khf[2 * sub], khf[2 * sub + 1]);
                }
            }
        }

        // ---- causal mask (tiles overlapping the diagonal) ----
        if (kt >= 2 * qt) {
#pragma unroll
            for (int nf = 0; nf < 8; ++nf)
#pragma unroll
                for (int j = 0; j < 4; ++j) {
                    int rw = q0 + warp * 16 + r_lo + ((j >> 1) << 3);
                    int cl = k0 + nf * 8 + 2 * (lane & 3) + (j & 1);
                    if (cl > rw) sacc[nf][j] = -1e30f;
                }
        }

        // ---- warp-local online softmax (rows pr0, pr1) ----
        float mx0 = -1e30f, mx1 = -1e30f;
#pragma unroll
        for (int nf = 0; nf < 8; ++nf) {
            mx0 = fmaxf(mx0, fmaxf(sacc[nf][0], sacc[nf][1]));
            mx1 = fmaxf(mx1, fmaxf(sacc[nf][2], sacc[nf][3]));
        }
        mx0 = fmaxf(mx0, __shfl_xor_sync(0xFFFFFFFFu, mx0, 1));
        mx0 = fmaxf(mx0, __shfl_xor_sync(0xFFFFFFFFu, mx0, 2));
        mx1 = fmaxf(mx1, __shfl_xor_sync(0xFFFFFFFFu, mx1, 1));
        mx1 = fmaxf(mx1, __shfl_xor_sync(0xFFFFFFFFu, mx1, 2));

        float mn0 = fmaxf(m0, mx0), mn1 = fmaxf(m1, mx1);
        float al0 = __expf(m0 - mn0), al1 = __expf(m1 - mn1);
        m0 = mn0; m1 = mn1;

        float rs0 = 0.0f, rs1 = 0.0f;
#pragma unroll
        for (int nf = 0; nf < 8; ++nf) {
            float p00 = __expf(sacc[nf][0] - mn0);
            float p01 = __expf(sacc[nf][1] - mn0);
            float p10 = __expf(sacc[nf][2] - mn1);
            float p11 = __expf(sacc[nf][3] - mn1);
            rs0 += p00 + p01;
            rs1 += p10 + p11;
            uint32_t lo, hi;
            hi = packsplit2(p00, p01, lo);
            uint32_t off0 = (uint32_t)(pr0 * 128 + ((nf ^ (pr0 & 7)) << 4) + 4 * (lane & 3));
            *(uint32_t*)(smem + F3_PH + off0) = hi;
            *(uint32_t*)(smem + F3_PL + off0) = lo;
            hi = packsplit2(p10, p11, lo);
            uint32_t off1 = (uint32_t)(pr1 * 128 + ((nf ^ (pr1 & 7)) << 4) + 4 * (lane & 3));
            *(uint32_t*)(smem + F3_PH + off1) = hi;
            *(uint32_t*)(smem + F3_PL + off1) = lo;
        }
        rs0 += __shfl_xor_sync(0xFFFFFFFFu, rs0, 1);
        rs0 += __shfl_xor_sync(0xFFFFFFFFu, rs0, 2);
        rs1 += __shfl_xor_sync(0xFFFFFFFFu, rs1, 1);
        rs1 += __shfl_xor_sync(0xFFFFFFFFu, rs1, 2);
        l0 = l0 * al0 + rs0;
        l1 = l1 * al1 + rs1;

#pragma unroll
        for (int ng = 0; ng < 16; ++ng) {
            acc[ng][0] *= al0; acc[ng][1] *= al0;
            acc[ng][2] *= al1; acc[ng][3] *= al1;
        }
        __syncwarp();   // P rows are warp-private: warp ordering suffices

        // ---- O += P . V  (3-plane; V via ldmatrix.trans) ----
        const uint32_t vb = kvb + 32768;
#pragma unroll
        for (int t = 0; t < 4; ++t) {
            uint32_t ph[4], pl[4];
            uint32_t pa = a_addr(su + F3_PH, warp * 16, t * 2, lane, 128);
            LDSM_X4(ph[0], ph[1], ph[2], ph[3], pa);
            LDSM_X4(pl[0], pl[1], pl[2], pl[3], pa + (F3_PL - F3_PH));
#pragma unroll
            for (int ng = 0; ng < 16; ng += 2) {
                uint32_t vh[4], vl[4];
                uint32_t va = a_addr(vb, t * 16, ng, lane, 256);
                LDSM_X4_T(vh[0], vh[1], vh[2], vh[3], va);
                LDSM_X4_T(vl[0], vl[1], vl[2], vl[3], va + 16384);
                MMA_BF16(acc[ng],     ph, vh[0], vh[1]);
                MMA_BF16(acc[ng],     ph, vl[0], vl[1]);
                MMA_BF16(acc[ng],     pl, vh[0], vh[1]);
                MMA_BF16(acc[ng + 1], ph, vh[2], vh[3]);
                MMA_BF16(acc[ng + 1], ph, vl[2], vl[3]);
                MMA_BF16(acc[ng + 1], pl, vh[2], vh[3]);
            }
        }
        __syncwarp();   // P reads done before next-iter overwrite
    }

    // ---- finalize: write context directly as bf16 hi/lo GEMM planes ----
    const float inv0 = 1.0f / l0, inv1 = 1.0f / l1;
    const int row0 = b * SEQ + q0 + warp * 16 + r_lo;   // global token row
    const size_t crow = (size_t)DMODEL * 2;             // plane row stride
#pragma unroll
    for (int ng = 0; ng < 16; ++ng) {
        int col = h * DHEAD + ng * 8 + 2 * (lane & 3);
        uint32_t lo, hi;
        hi = packsplit2(acc[ng][0] * inv0, acc[ng][1] * inv0, lo);
        size_t a0 = (size_t)row0 * crow + (size_t)col * 2;
        *(uint32_t*)(Ch + a0) = hi;
        *(uint32_t*)(Cl + a0) = lo;
        hi = packsplit2(acc[ng][2] * inv1, acc[ng][3] * inv1, lo);
        size_t a1 = a0 + 8 * crow;
        *(uint32_t*)(Ch + a1) = hi;
        *(uint32_t*)(Cl + a1) = lo;
    }
}

// ---------------------------------------------------------------------------
// kernel_launch
// Inputs (metadata order): x, cos, sin, Wq, Wk, Wv, Wo  (all fp32)
// Output: (B, S, D_MODEL) fp32
// ---------------------------------------------------------------------------
extern "C" void kernel_launch(void* const* d_in, const int* in_sizes, int n_in,
                              void* d_out, int out_size)
{
    const float* x    = (const float*)d_in[0];
    const float* cosT = (const float*)d_in[1];
    const float* sinT = (const float*)d_in[2];
    const float* Wq   = (const float*)d_in[3];
    const float* Wk   = (const float*)d_in[4];
    const float* Wv   = (const float*)d_in[5];
    const float* Wo   = (const float*)d_in[6];
    float* out = (float*)d_out;

    float *qp, *kp, *vp;
    uint8_t *qh, *ql, *kh, *kl, *vh, *vl;
    uint8_t *xh, *xl, *ch, *cl;
    uint8_t *wqh, *wql, *wkh, *wkl, *wvh, *wvl, *woh, *wol;
    cudaGetSymbolAddress((void**)&qp, g_Q);
    cudaGetSymbolAddress((void**)&kp, g_K);
    cudaGetSymbolAddress((void**)&vp, g_V);
    cudaGetSymbolAddress((void**)&qh, g_Qh);
    cudaGetSymbolAddress((void**)&ql, g_Ql);
    cudaGetSymbolAddress((void**)&kh, g_Kh);
    cudaGetSymbolAddress((void**)&kl, g_Kl);
    cudaGetSymbolAddress((void**)&vh, g_Vh);
    cudaGetSymbolAddress((void**)&vl, g_Vl);
    cudaGetSymbolAddress((void**)&xh, g_Xh);
    cudaGetSymbolAddress((void**)&xl, g_Xl);
    cudaGetSymbolAddress((void**)&ch, g_Ch);
    cudaGetSymbolAddress((void**)&cl, g_Cl);
    cudaGetSymbolAddress((void**)&wqh, g_Wqh);
    cudaGetSymbolAddress((void**)&wql, g_Wql);
    cudaGetSymbolAddress((void**)&wkh, g_Wkh);
    cudaGetSymbolAddress((void**)&wkl, g_Wkl);
    cudaGetSymbolAddress((void**)&wvh, g_Wvh);
    cudaGetSymbolAddress((void**)&wvl, g_Wvl);
    cudaGetSymbolAddress((void**)&woh, g_Woh);
    cudaGetSymbolAddress((void**)&wol, g_Wol);

    cudaFuncSetAttribute(gemm_mma2_kernel,
                         cudaFuncAttributeMaxDynamicSharedMemorySize, G2_SMEM);
    cudaFuncSetAttribute(flash_attn_mma3_kernel,
                         cudaFuncAttributeMaxDynamicSharedMemorySize, F3_SMEM);

    const int xq8 = NTOK * DMODEL / 8;
    const int wq8 = DMODEL * DMODEL / 8;

    // Pre-split inputs to bf16 hi/lo planes
    split_planes_kernel<<<(xq8 + 255) / 256, 256>>>(x,  xh,  xl,  xq8);
    split_planes_kernel<<<(wq8 + 255) / 256, 256>>>(Wq, wqh, wql, wq8);
    split_planes_kernel<<<(wq8 + 255) / 256, 256>>>(Wk, wkh, wkl, wq8);
    split_planes_kernel<<<(wq8 + 255) / 256, 256>>>(Wv, wvh, wvl, wq8);
    split_planes_kernel<<<(wq8 + 255) / 256, 256>>>(Wo, woh, wol, wq8);

    dim3 ggrid(DMODEL / 128, NTOK / 128);   // (16, 32)

    // QKV projections
    gemm_mma2_kernel<<<ggrid, 256, G2_SMEM>>>(xh, xl, wqh, wql, qp, NTOK, DMODEL, DMODEL);
    gemm_mma2_kernel<<<ggrid, 256, G2_SMEM>>>(xh, xl, wkh, wkl, kp, NTOK, DMODEL, DMODEL);
    gemm_mma2_kernel<<<ggrid, 256, G2_SMEM>>>(xh, xl, wvh, wvl, vp, NTOK, DMODEL, DMODEL);

    // RoPE + FA plane conversion
    int cvt_threads = NTOK * NHEADS * 16;
    rope_convert_kernel<<<(cvt_threads + 255) / 256, 256>>>(
        qp, kp, vp, cosT, sinT, qh, ql, kh, kl, vh, vl);

    // Causal flash attention (writes context planes directly)
    dim3 fgrid(SEQ / 128, NHEADS, BATCH);   // (16, 16, 2)
    flash_attn_mma3_kernel<<<fgrid, 256, F3_SMEM>>>(qh, ql, kh, kl, vh, vl, ch, cl);

    // Output projection
    gemm_mma2_kernel<<<ggrid, 256, G2_SMEM>>>(ch, cl, woh, wol, out, NTOK, DMODEL, DMODEL);
}